// round 10
// baseline (speedup 1.0000x reference)
#include <cuda_runtime.h>
#include <cuda_fp16.h>
#include <cstdint>

#define NTOK   4096          // B*N = 2*2048
#define DM     512
#define NSEQ   2048
#define NHEADS 8
#define DK     64

#define QSCALE 64.0f
#define KSCALE 2048.0f
#define ATT_CSCALE (1.0f / (64.0f * 2048.0f))
#define OH_CSCALE  (1.0f / (64.0f * 2048.0f))

// ---------------- scratch (__device__ globals; no allocs allowed) ----------
__device__ float g_Vf[NTOK * DM];                             // V fp32
__device__ __half g_XH[3 * NTOK * DM], g_XL[3 * NTOK * DM];   // q,k,v hi/lo
__device__ __half g_WH[4 * DM * DM];                          // Wq,Wk,Wv,Wo (hi)
__device__ __half g_Qnh[NTOK * DM], g_Qnl[NTOK * DM];         // Qn * 64 (exact pair)
__device__ __half g_Kh[NTOK * DM];                            // elu(K)+1, fp16
__device__ float g_ksum[1024];                                // per (b, d) col sums
__device__ float g_Spart[32 * 16 * DK * DK];                  // scaled x2048
__device__ float g_S[16 * DK * DK];                           // scaled x2048
__device__ __half g_OHh[NTOK * DM], g_OHl[NTOK * DM];

// ---------------- helpers ---------------------------------------------------
__device__ __forceinline__ void cvt_split(float x, __half& hi, __half& lo) {
    hi = __float2half_rn(x);
    lo = __float2half_rn(x - __half2float(hi));
}
__device__ __forceinline__ uint32_t pack2(__half a, __half b) {
    __half2 t(a, b);
    return *reinterpret_cast<uint32_t*>(&t);
}
__device__ __forceinline__ uint32_t smem_u32(const void* p) {
    uint32_t a;
    asm("{ .reg .u64 t; cvta.to.shared.u64 t, %1; cvt.u32.u64 %0, t; }" : "=r"(a) : "l"(p));
    return a;
}
__device__ __forceinline__ void mma16816(float* c, const uint32_t* a, const uint32_t* b) {
    asm volatile(
        "mma.sync.aligned.m16n8k16.row.col.f32.f16.f16.f32 "
        "{%0,%1,%2,%3},{%4,%5,%6,%7},{%8,%9},{%0,%1,%2,%3};"
        : "+f"(c[0]), "+f"(c[1]), "+f"(c[2]), "+f"(c[3])
        : "r"(a[0]), "r"(a[1]), "r"(a[2]), "r"(a[3]), "r"(b[0]), "r"(b[1]));
}
__device__ __forceinline__ void ldsm4(uint32_t* r, uint32_t a) {
    asm volatile("ldmatrix.sync.aligned.m8n8.x4.shared.b16 {%0,%1,%2,%3},[%4];"
                 : "=r"(r[0]), "=r"(r[1]), "=r"(r[2]), "=r"(r[3]) : "r"(a));
}
__device__ __forceinline__ float elup1(float x) {
    return (x > 0.f) ? x + 1.f : expf(x);
}

// ---------------- one-shot fp32 -> fp16 conversion (inputs hi/lo, weights hi)
#define NI4 (NTOK * DM / 4)
#define NW4 (DM * DM / 4)

__global__ void cvt_all_kernel(const float* __restrict__ q, const float* __restrict__ k,
                               const float* __restrict__ v,
                               const float* __restrict__ Wq, const float* __restrict__ Wk,
                               const float* __restrict__ Wv, const float* __restrict__ Wo,
                               __half* __restrict__ XH, __half* __restrict__ XL,
                               __half* __restrict__ WH,
                               float* __restrict__ ksum)
{
    if (blockIdx.x < 4) ksum[blockIdx.x * 256 + threadIdx.x] = 0.f;
    long long i4 = (long long)blockIdx.x * 256 + threadIdx.x;
    float4 vv;
    if (i4 < 3LL * NI4) {
        int w = (int)(i4 / NI4);
        const float* src = (w == 0) ? q : (w == 1) ? k : v;
        long long off = i4;
        i4 -= (long long)w * NI4;
        vv = reinterpret_cast<const float4*>(src)[i4];
        __half a, b, c, d, e, f, g, hh;
        cvt_split(vv.x, a, e); cvt_split(vv.y, b, f);
        cvt_split(vv.z, c, g); cvt_split(vv.w, d, hh);
        uint2 ph; ph.x = pack2(a, b); ph.y = pack2(c, d);
        uint2 pl; pl.x = pack2(e, f); pl.y = pack2(g, hh);
        reinterpret_cast<uint2*>(XH)[off] = ph;
        reinterpret_cast<uint2*>(XL)[off] = pl;
    } else {
        long long j = i4 - 3LL * NI4;
        int w = (int)(j / NW4);
        const float* src = (w == 0) ? Wq : (w == 1) ? Wk : (w == 2) ? Wv : Wo;
        long long loc = j - (long long)w * NW4;
        vv = reinterpret_cast<const float4*>(src)[loc];
        uint2 ph;
        ph.x = pack2(__float2half_rn(vv.x), __float2half_rn(vv.y));
        ph.y = pack2(__float2half_rn(vv.z), __float2half_rn(vv.w));
        reinterpret_cast<uint2*>(WH)[j] = ph;
    }
}

// ---------------- shared GEMM plumbing --------------------------------------
#define GST   40                  // padded row: 32 elems + 8 (80B; LDSM conflict-free)
#define TILEB (128 * GST * 2)     // 10240 B per tile

// ---------------- fused projection kernel (zbase selects q/k vs v) ----------
__global__ __launch_bounds__(256, 2)
void proj_kernel(const __half* __restrict__ XH, const __half* __restrict__ XL,
                 const __half* __restrict__ WH,
                 const float* __restrict__ bq, const float* __restrict__ bk,
                 const float* __restrict__ bv,
                 __half* __restrict__ Qnh, __half* __restrict__ Qnl,
                 __half* __restrict__ Kh, float* __restrict__ Vf,
                 float* __restrict__ ksum, int zbase)
{
    extern __shared__ __half smem[];
    constexpr int STAGEB = 3 * TILEB;
    int zb = blockIdx.z + zbase;
    const __half* Ahi = XH + (long long)zb * NTOK * DM;
    const __half* Alo = XL + (long long)zb * NTOK * DM;
    const __half* Bhi = WH + (long long)zb * DM * DM;
    const float* bias = (zb == 0) ? bq : (zb == 1) ? bk : bv;

    int m0 = blockIdx.y * 128, n0 = blockIdx.x * 128;
    int tid = threadIdx.x, lane = tid & 31, warp = tid >> 5;
    int wm = (warp >> 1) * 32;
    int wn = (warp & 1) * 64;
    int grp = lane >> 2, tig = lane & 3;
    uint32_t sb = smem_u32(smem);

    int aoff = (wm + (lane & 15)) * GST + ((lane >> 4) << 3);
    int boff = (wn + ((lane >> 4) << 3) + (lane & 7)) * GST + (((lane >> 3) & 1) << 3);

    float acc[2][8][4];
    #pragma unroll
    for (int i = 0; i < 2; i++)
        #pragma unroll
        for (int j = 0; j < 8; j++)
            #pragma unroll
            for (int l = 0; l < 4; l++) acc[i][j][l] = 0.f;

    auto issue = [&](int s, int kt) {
        #pragma unroll
        for (int j = 0; j < 6; j++) {
            int id = tid + j * 256;
            int tile = id >> 9;
            int w = id & 511;
            int r = w >> 2, ce = (w & 3) * 8;
            const __half* src;
            if (tile == 0)      src = Ahi + (long long)(m0 + r) * DM + kt + ce;
            else if (tile == 1) src = Alo + (long long)(m0 + r) * DM + kt + ce;
            else                src = Bhi + (long long)(n0 + r) * DM + kt + ce;
            uint32_t d = sb + (uint32_t)(s * STAGEB + tile * TILEB) + (uint32_t)(r * GST + ce) * 2u;
            asm volatile("cp.async.cg.shared.global [%0],[%1],16;\n" :: "r"(d), "l"(src));
        }
        asm volatile("cp.async.commit_group;\n" ::);
    };

    issue(0, 0);
    for (int i = 0; i < 16; i++) {
        int cur = i & 1;
        if (i + 1 < 16) {
            issue(cur ^ 1, (i + 1) << 5);
            asm volatile("cp.async.wait_group 1;\n" ::);
        } else {
            asm volatile("cp.async.wait_group 0;\n" ::);
        }
        __syncthreads();
        uint32_t sA  = sb + cur * STAGEB;
        uint32_t sAl = sA + TILEB;
        uint32_t sB  = sA + 2 * TILEB;

        #pragma unroll
        for (int kk = 0; kk < 32; kk += 16) {
            uint32_t ah[2][4], al[2][4], bf[4][4];
            #pragma unroll
            for (int mi = 0; mi < 2; mi++)
                ldsm4(ah[mi], sA + (uint32_t)(aoff + mi * 16 * GST + kk) * 2u);
            #pragma unroll
            for (int n2 = 0; n2 < 4; n2++)
                ldsm4(bf[n2], sB + (uint32_t)(boff + n2 * 16 * GST + kk) * 2u);
            #pragma unroll
            for (int mi = 0; mi < 2; mi++)
                #pragma unroll
                for (int n2 = 0; n2 < 4; n2++) {
                    mma16816(acc[mi][2 * n2],     ah[mi], bf[n2]);
                    mma16816(acc[mi][2 * n2 + 1], ah[mi], bf[n2] + 2);
                }
            #pragma unroll
            for (int mi = 0; mi < 2; mi++)
                ldsm4(al[mi], sAl + (uint32_t)(aoff + mi * 16 * GST + kk) * 2u);
            #pragma unroll
            for (int mi = 0; mi < 2; mi++)
                #pragma unroll
                for (int n2 = 0; n2 < 4; n2++) {
                    mma16816(acc[mi][2 * n2],     al[mi], bf[n2]);
                    mma16816(acc[mi][2 * n2 + 1], al[mi], bf[n2] + 2);
                }
        }
        __syncthreads();
    }

    // ---- epilogue: bias (+ elu+1 for q,k) ----
    #pragma unroll
    for (int mi = 0; mi < 2; mi++)
        #pragma unroll
        for (int ni = 0; ni < 8; ni++) {
            int col = n0 + wn + ni * 8 + tig * 2;
            float bb0 = __ldg(&bias[col]), bb1 = __ldg(&bias[col + 1]);
            acc[mi][ni][0] += bb0; acc[mi][ni][1] += bb1;
            acc[mi][ni][2] += bb0; acc[mi][ni][3] += bb1;
            if (zb < 2) {
                acc[mi][ni][0] = elup1(acc[mi][ni][0]);
                acc[mi][ni][1] = elup1(acc[mi][ni][1]);
                acc[mi][ni][2] = elup1(acc[mi][ni][2]);
                acc[mi][ni][3] = elup1(acc[mi][ni][3]);
            }
        }

    if (zb == 0) {
        // Q: per-head row-normalize (warp's 64 cols = one full head)
        #pragma unroll
        for (int mi = 0; mi < 2; mi++) {
            float s0 = 0.f, s1 = 0.f;
            #pragma unroll
            for (int ni = 0; ni < 8; ni++) {
                s0 += acc[mi][ni][0] + acc[mi][ni][1];
                s1 += acc[mi][ni][2] + acc[mi][ni][3];
            }
            s0 += __shfl_xor_sync(0xffffffffu, s0, 1);
            s0 += __shfl_xor_sync(0xffffffffu, s0, 2);
            s1 += __shfl_xor_sync(0xffffffffu, s1, 1);
            s1 += __shfl_xor_sync(0xffffffffu, s1, 2);
            float inv0 = QSCALE / (s0 + 1e-8f);
            float inv1 = QSCALE / (s1 + 1e-8f);
            int r0 = m0 + wm + mi * 16 + grp;
            #pragma unroll
            for (int ni = 0; ni < 8; ni++) {
                int col = n0 + wn + ni * 8 + tig * 2;
                __half h0, l0, h1, l1;
                cvt_split(acc[mi][ni][0] * inv0, h0, l0);
                cvt_split(acc[mi][ni][1] * inv0, h1, l1);
                *reinterpret_cast<uint32_t*>(&Qnh[(long long)r0 * DM + col]) = pack2(h0, h1);
                *reinterpret_cast<uint32_t*>(&Qnl[(long long)r0 * DM + col]) = pack2(l0, l1);
                cvt_split(acc[mi][ni][2] * inv1, h0, l0);
                cvt_split(acc[mi][ni][3] * inv1, h1, l1);
                *reinterpret_cast<uint32_t*>(&Qnh[(long long)(r0 + 8) * DM + col]) = pack2(h0, h1);
                *reinterpret_cast<uint32_t*>(&Qnl[(long long)(r0 + 8) * DM + col]) = pack2(l0, l1);
            }
        }
    } else if (zb == 1) {
        // K: store fp16 + column-sum atomics
        int bb = m0 >> 11;
        #pragma unroll
        for (int ni = 0; ni < 8; ni++) {
            int col = n0 + wn + ni * 8 + tig * 2;
            float c0 = 0.f, c1 = 0.f;
            #pragma unroll
            for (int mi = 0; mi < 2; mi++) {
                int r0 = m0 + wm + mi * 16 + grp;
                c0 += acc[mi][ni][0] + acc[mi][ni][2];
                c1 += acc[mi][ni][1] + acc[mi][ni][3];
                *reinterpret_cast<uint32_t*>(&Kh[(long long)r0 * DM + col]) =
                    pack2(__float2half_rn(acc[mi][ni][0]), __float2half_rn(acc[mi][ni][1]));
                *reinterpret_cast<uint32_t*>(&Kh[(long long)(r0 + 8) * DM + col]) =
                    pack2(__float2half_rn(acc[mi][ni][2]), __float2half_rn(acc[mi][ni][3]));
            }
            c0 += __shfl_xor_sync(0xffffffffu, c0, 4);
            c0 += __shfl_xor_sync(0xffffffffu, c0, 8);
            c0 += __shfl_xor_sync(0xffffffffu, c0, 16);
            c1 += __shfl_xor_sync(0xffffffffu, c1, 4);
            c1 += __shfl_xor_sync(0xffffffffu, c1, 8);
            c1 += __shfl_xor_sync(0xffffffffu, c1, 16);
            if (grp == 0) {
                atomicAdd(&ksum[bb * DM + col], c0);
                atomicAdd(&ksum[bb * DM + col + 1], c1);
            }
        }
    } else {
        // V: fp32
        #pragma unroll
        for (int mi = 0; mi < 2; mi++)
            #pragma unroll
            for (int ni = 0; ni < 8; ni++) {
                int row = m0 + wm + mi * 16 + grp;
                int col = n0 + wn + ni * 8 + tig * 2;
                *reinterpret_cast<float2*>(Vf + (long long)row * DM + col) =
                    make_float2(acc[mi][ni][0], acc[mi][ni][1]);
                *reinterpret_cast<float2*>(Vf + (long long)(row + 8) * DM + col) =
                    make_float2(acc[mi][ni][2], acc[mi][ni][3]);
            }
    }
}

// ---------------- final projection: out = OH @ Wo^T + bo (2-term) -----------
__global__ __launch_bounds__(256, 2)
void mm2_kernel(const __half* __restrict__ Ahi, const __half* __restrict__ Alo,
                const __half* __restrict__ Bhi,
                float* __restrict__ C,
                const float* __restrict__ bias)
{
    extern __shared__ __half smem[];
    constexpr int STAGEB = 3 * TILEB;

    int m0 = blockIdx.y * 128, n0 = blockIdx.x * 128;
    int tid = threadIdx.x, lane = tid & 31, warp = tid >> 5;
    int wm = (warp >> 1) * 32;
    int wn = (warp & 1) * 64;
    int grp = lane >> 2, tig = lane & 3;
    uint32_t sb = smem_u32(smem);

    int aoff = (wm + (lane & 15)) * GST + ((lane >> 4) << 3);
    int boff = (wn + ((lane >> 4) << 3) + (lane & 7)) * GST + (((lane >> 3) & 1) << 3);

    float acc[2][8][4];
    #pragma unroll
    for (int i = 0; i < 2; i++)
        #pragma unroll
        for (int j = 0; j < 8; j++)
            #pragma unroll
            for (int l = 0; l < 4; l++) acc[i][j][l] = 0.f;

    auto issue = [&](int s, int kt) {
        #pragma unroll
        for (int j = 0; j < 6; j++) {
            int id = tid + j * 256;
            int tile = id >> 9;
            int w = id & 511;
            int r = w >> 2, ce = (w & 3) * 8;
            const __half* src;
            if (tile == 0)      src = Ahi + (long long)(m0 + r) * DM + kt + ce;
            else if (tile == 1) src = Alo + (long long)(m0 + r) * DM + kt + ce;
            else                src = Bhi + (long long)(n0 + r) * DM + kt + ce;
            uint32_t d = sb + (uint32_t)(s * STAGEB + tile * TILEB) + (uint32_t)(r * GST + ce) * 2u;
            asm volatile("cp.async.cg.shared.global [%0],[%1],16;\n" :: "r"(d), "l"(src));
        }
        asm volatile("cp.async.commit_group;\n" ::);
    };

    issue(0, 0);
    for (int i = 0; i < 16; i++) {
        int cur = i & 1;
        if (i + 1 < 16) {
            issue(cur ^ 1, (i + 1) << 5);
            asm volatile("cp.async.wait_group 1;\n" ::);
        } else {
            asm volatile("cp.async.wait_group 0;\n" ::);
        }
        __syncthreads();
        uint32_t sA  = sb + cur * STAGEB;
        uint32_t sAl = sA + TILEB;
        uint32_t sB  = sA + 2 * TILEB;

        #pragma unroll
        for (int kk = 0; kk < 32; kk += 16) {
            uint32_t ah[2][4], al[2][4], bf[4][4];
            #pragma unroll
            for (int mi = 0; mi < 2; mi++)
                ldsm4(ah[mi], sA + (uint32_t)(aoff + mi * 16 * GST + kk) * 2u);
            #pragma unroll
            for (int n2 = 0; n2 < 4; n2++)
                ldsm4(bf[n2], sB + (uint32_t)(boff + n2 * 16 * GST + kk) * 2u);
            #pragma unroll
            for (int mi = 0; mi < 2; mi++)
                #pragma unroll
                for (int n2 = 0; n2 < 4; n2++) {
                    mma16816(acc[mi][2 * n2],     ah[mi], bf[n2]);
                    mma16816(acc[mi][2 * n2 + 1], ah[mi], bf[n2] + 2);
                }
            #pragma unroll
            for (int mi = 0; mi < 2; mi++)
                ldsm4(al[mi], sAl + (uint32_t)(aoff + mi * 16 * GST + kk) * 2u);
            #pragma unroll
            for (int mi = 0; mi < 2; mi++)
                #pragma unroll
                for (int n2 = 0; n2 < 4; n2++) {
                    mma16816(acc[mi][2 * n2],     al[mi], bf[n2]);
                    mma16816(acc[mi][2 * n2 + 1], al[mi], bf[n2] + 2);
                }
        }
        __syncthreads();
    }

    #pragma unroll
    for (int mi = 0; mi < 2; mi++) {
        #pragma unroll
        for (int ni = 0; ni < 8; ni++) {
            int row = m0 + wm + mi * 16 + grp;
            int col = n0 + wn + ni * 8 + tig * 2;
            float bb0 = __ldg(&bias[col]), bb1 = __ldg(&bias[col + 1]);
            float2 p0 = make_float2(acc[mi][ni][0] + bb0, acc[mi][ni][1] + bb1);
            float2 p1 = make_float2(acc[mi][ni][2] + bb0, acc[mi][ni][3] + bb1);
            __stcs(reinterpret_cast<float2*>(C + (long long)row * DM + col), p0);
            __stcs(reinterpret_cast<float2*>(C + (long long)(row + 8) * DM + col), p1);
        }
    }
}

// ---------------- att: 1-term fp16 GEMM with in-smem K normalization --------
#define ATT_SMEM (2 * 2 * TILEB + 256)   // 2 stages x {A,B} + scale table

__global__ __launch_bounds__(256, 2)
void att_kernel(const __half* __restrict__ Qnh, const __half* __restrict__ Kh,
                const float* __restrict__ ksum, float* __restrict__ att)
{
    extern __shared__ char dsm[];
    int tid = threadIdx.x;
    int bh = blockIdx.z;
    int b = bh >> 3, h = bh & 7;
    const __half* A = Qnh + (long long)b * NSEQ * DM + h * DK;
    const __half* B = Kh + (long long)b * NSEQ * DM + h * DK;
    float* C = att + (long long)bh * NSEQ * NSEQ;
    float* sc = reinterpret_cast<float*>(dsm + 4 * TILEB);

    int m0 = blockIdx.y * 128, n0 = blockIdx.x * 128;
    int lane = tid & 31, warp = tid >> 5;
    int wm = (warp >> 1) * 32;
    int wn = (warp & 1) * 64;
    int grp = lane >> 2, tig = lane & 3;
    uint32_t sb = smem_u32(dsm);
    constexpr int STAGEB = 2 * TILEB;

    int aoff = (wm + (lane & 15)) * GST + ((lane >> 4) << 3);
    int boff = (wn + ((lane >> 4) << 3) + (lane & 7)) * GST + (((lane >> 3) & 1) << 3);

    float acc[2][8][4];
    #pragma unroll
    for (int i = 0; i < 2; i++)
        #pragma unroll
        for (int j = 0; j < 8; j++)
            #pragma unroll
            for (int l = 0; l < 4; l++) acc[i][j][l] = 0.f;

    auto issue = [&](int s, int kt) {
        #pragma unroll
        for (int j = 0; j < 4; j++) {
            int id = tid + j * 256;
            int tile = id >> 9;
            int w = id & 511;
            int r = w >> 2, ce = (w & 3) * 8;
            const __half* src = (tile == 0)
                ? A + (long long)(m0 + r) * DM + kt + ce
                : B + (long long)(n0 + r) * DM + kt + ce;
            uint32_t d = sb + (uint32_t)(s * STAGEB + tile * TILEB) + (uint32_t)(r * GST + ce) * 2u;
            asm volatile("cp.async.cg.shared.global [%0],[%1],16;\n" :: "r"(d), "l"(src));
        }
        asm volatile("cp.async.commit_group;\n" ::);
    };

    issue(0, 0);
    if (tid < 64) sc[tid] = KSCALE / (__ldg(&ksum[b * DM + h * DK + tid]) + 1e-8f);
    #pragma unroll
    for (int i = 0; i < 2; i++) {
        if (i == 0) {
            issue(1, 32);
            asm volatile("cp.async.wait_group 1;\n" ::);
        } else {
            asm volatile("cp.async.wait_group 0;\n" ::);
        }
        __syncthreads();
        // normalize the K tile (B operand) in smem: x KSCALE/ksum[d]
        {
            char* bbase = dsm + i * STAGEB + TILEB;
            #pragma unroll
            for (int j = 0; j < 8; j++) {
                int id = tid + j * 256;
                int r = id >> 4, c = (id & 15) * 2;
                __half2* p = reinterpret_cast<__half2*>(bbase + (uint32_t)(r * GST + c) * 2u);
                float2 f = __half22float2(*p);
                f.x *= sc[i * 32 + c];
                f.y *= sc[i * 32 + c + 1];
                *p = __floats2half2_rn(f.x, f.y);
            }
        }
        __syncthreads();
        uint32_t sA = sb + i * STAGEB;
        uint32_t sB = sA + TILEB;
        #pragma unroll
        for (int kk = 0; kk < 32; kk += 16) {
            uint32_t ah[2][4], bf[4][4];
            #pragma unroll
            for (int mi = 0; mi < 2; mi++)
                ldsm4(ah[mi], sA + (uint32_t)(aoff + mi * 16 * GST + kk) * 2u);
            #pragma unroll
            for (int n2 = 0; n2 < 4; n2++)
                ldsm4(bf[n2], sB + (uint32_t)(boff + n2 * 16 * GST + kk) * 2u);
            #pragma unroll
            for (int mi = 0; mi < 2; mi++)
                #pragma unroll
                for (int n2 = 0; n2 < 4; n2++) {
                    mma16816(acc[mi][2 * n2],     ah[mi], bf[n2]);
                    mma16816(acc[mi][2 * n2 + 1], ah[mi], bf[n2] + 2);
                }
        }
        __syncthreads();
    }

    #pragma unroll
    for (int mi = 0; mi < 2; mi++) {
        #pragma unroll
        for (int ni = 0; ni < 8; ni++) {
            int row = m0 + wm + mi * 16 + grp;
            int col = n0 + wn + ni * 8 + tig * 2;
            float2 p0 = make_float2(acc[mi][ni][0] * ATT_CSCALE, acc[mi][ni][1] * ATT_CSCALE);
            float2 p1 = make_float2(acc[mi][ni][2] * ATT_CSCALE, acc[mi][ni][3] * ATT_CSCALE);
            __stcs(reinterpret_cast<float2*>(C + (long long)row * NSEQ + col), p0);
            __stcs(reinterpret_cast<float2*>(C + (long long)(row + 8) * NSEQ + col), p1);
        }
    }
}

// ---------------- spart: Kn^T V chunk partials (fp32 SIMT) ------------------
__global__ void spart_kernel(const __half* __restrict__ Kh, const float* __restrict__ ksum,
                             const float* __restrict__ Vf, float* __restrict__ Spart)
{
    __shared__ float Kt[64 * 64];
    __shared__ float Vt[64 * 64];
    __shared__ float sc[64];
    int chunk = blockIdx.x, bh = blockIdx.y;
    int b = bh >> 3, h = bh & 7;
    int tid = threadIdx.x;
    int d = tid & 63, qq = tid >> 6;
    if (tid < 64) sc[tid] = KSCALE / (__ldg(&ksum[b * DM + h * DK + tid]) + 1e-8f);
    __syncthreads();
    float acc[16];
    #pragma unroll
    for (int j = 0; j < 16; j++) acc[j] = 0.f;
    long long base = ((long long)b * NSEQ + chunk * 64) * DM + h * DK;
    #pragma unroll
    for (int j = 0; j < 16; j++) {
        int idd = tid + j * 256;
        int nl = idd >> 6, dd = idd & 63;
        Kt[nl * 64 + dd] = __half2float(Kh[base + (long long)nl * DM + dd]) * sc[dd];
        Vt[nl * 64 + dd] = Vf[base + (long long)nl * DM + dd];
    }
    __syncthreads();
    for (int nn = 0; nn < 64; nn++) {
        float kv = Kt[nn * 64 + d];
        const float4* vr = reinterpret_cast<const float4*>(&Vt[nn * 64 + qq * 16]);
        #pragma unroll
        for (int j4 = 0; j4 < 4; j4++) {
            float4 v = vr[j4];
            acc[j4 * 4 + 0] += kv * v.x;
            acc[j4 * 4 + 1] += kv * v.y;
            acc[j4 * 4 + 2] += kv * v.z;
            acc[j4 * 4 + 3] += kv * v.w;
        }
    }
    float* o = Spart + ((long long)chunk * 16 + bh) * (DK * DK) + d * DK + qq * 16;
    #pragma unroll
    for (int j4 = 0; j4 < 4; j4++)
        reinterpret_cast<float4*>(o)[j4] =
            make_float4(acc[j4 * 4], acc[j4 * 4 + 1], acc[j4 * 4 + 2], acc[j4 * 4 + 3]);
}

__global__ void s_reduce_kernel(const float* __restrict__ Spart, float* __restrict__ S) {
    int i = blockIdx.x * 1024 + threadIdx.x;
    float s = 0.f;
    #pragma unroll
    for (int c = 0; c < 32; c++) s += Spart[(long long)c * 65536 + i];
    S[i] = s;
}

// ---------------- OH = Qn @ S per (b,h) -------------------------------------
__global__ void oh_kernel(const __half* __restrict__ Qnh, const __half* __restrict__ Qnl,
                          const float* __restrict__ S,
                          __half* __restrict__ OHh, __half* __restrict__ OHl) {
    int mc = blockIdx.x;
    int bh = blockIdx.y;
    int b = bh >> 3, h = bh & 7;
    int t = threadIdx.x;
    int e4 = t & 15, r = t >> 4;
    __shared__ float Ss[64][64];
    __shared__ float Qs[16][64];
    #pragma unroll
    for (int j = 0; j < 16; j++) {
        int id = t + j * 256;
        Ss[id >> 6][id & 63] = S[(long long)bh * (DK * DK) + id];
    }
    for (int it = 0; it < 8; it++) {
        int mrow = mc * 128 + it * 16;
        __syncthreads();
        #pragma unroll
        for (int j = 0; j < 4; j++) {
            int id = t + j * 256;
            int rr = id >> 6, dd = id & 63;
            long long qidx = ((long long)b * NSEQ + mrow + rr) * DM + h * DK + dd;
            Qs[rr][dd] = __half2float(Qnh[qidx]) + __half2float(Qnl[qidx]);
        }
        __syncthreads();
        float4 a = make_float4(0.f, 0.f, 0.f, 0.f);
        #pragma unroll
        for (int dd = 0; dd < 64; dd++) {
            float qd = Qs[r][dd];
            float4 s4 = *reinterpret_cast<const float4*>(&Ss[dd][e4 * 4]);
            a.x += qd * s4.x; a.y += qd * s4.y; a.z += qd * s4.z; a.w += qd * s4.w;
        }
        __half h0, h1, h2, h3, l0, l1, l2, l3;
        cvt_split(a.x * OH_CSCALE, h0, l0); cvt_split(a.y * OH_CSCALE, h1, l1);
        cvt_split(a.z * OH_CSCALE, h2, l2); cvt_split(a.w * OH_CSCALE, h3, l3);
        long long oidx = ((long long)b * NSEQ + mrow + r) * DM + h * DK + e4 * 4;
        uint2 ph; ph.x = pack2(h0, h1); ph.y = pack2(h2, h3);
        uint2 pl; pl.x = pack2(l0, l1); pl.y = pack2(l2, l3);
        *reinterpret_cast<uint2*>(OHh + oidx) = ph;
        *reinterpret_cast<uint2*>(OHl + oidx) = pl;
    }
}

// ---------------- launch ----------------------------------------------------
extern "C" void kernel_launch(void* const* d_in, const int* in_sizes, int n_in,
                              void* d_out, int out_size) {
    const float* q  = (const float*)d_in[0];
    const float* k  = (const float*)d_in[1];
    const float* v  = (const float*)d_in[2];
    const float* Wq = (const float*)d_in[3];
    const float* bq = (const float*)d_in[4];
    const float* Wk = (const float*)d_in[5];
    const float* bk = (const float*)d_in[6];
    const float* Wv = (const float*)d_in[7];
    const float* bv = (const float*)d_in[8];
    const float* Wo = (const float*)d_in[9];
    const float* bo = (const float*)d_in[10];

    float* out = (float*)d_out;                       // [2,2048,512]
    float* att = out + (long long)NTOK * DM;          // [2,8,2048,2048]

    float *Vf, *ks, *Spart, *S;
    __half *XH, *XL, *WH, *Qnh, *Qnl, *Kh, *OHh, *OHl;
    cudaGetSymbolAddress((void**)&Vf, g_Vf);
    cudaGetSymbolAddress((void**)&ks, g_ksum);
    cudaGetSymbolAddress((void**)&Spart, g_Spart);
    cudaGetSymbolAddress((void**)&S, g_S);
    cudaGetSymbolAddress((void**)&XH, g_XH);  cudaGetSymbolAddress((void**)&XL, g_XL);
    cudaGetSymbolAddress((void**)&WH, g_WH);
    cudaGetSymbolAddress((void**)&Qnh, g_Qnh); cudaGetSymbolAddress((void**)&Qnl, g_Qnl);
    cudaGetSymbolAddress((void**)&Kh, g_Kh);
    cudaGetSymbolAddress((void**)&OHh, g_OHh); cudaGetSymbolAddress((void**)&OHl, g_OHl);

    constexpr int SMP = 2 * 3 * TILEB;   // 61440
    cudaFuncSetAttribute(proj_kernel, cudaFuncAttributeMaxDynamicSharedMemorySize, SMP);
    cudaFuncSetAttribute(mm2_kernel, cudaFuncAttributeMaxDynamicSharedMemorySize, SMP);
    cudaFuncSetAttribute(att_kernel, cudaFuncAttributeMaxDynamicSharedMemorySize, ATT_SMEM);

    static cudaStream_t s2 = nullptr;
    static cudaEvent_t evFork = nullptr, evJoin = nullptr;
    if (!s2) {
        cudaStreamCreateWithFlags(&s2, cudaStreamNonBlocking);
        cudaEventCreateWithFlags(&evFork, cudaEventDisableTiming);
        cudaEventCreateWithFlags(&evJoin, cudaEventDisableTiming);
    }

    // launch #0: one-shot conversions (+ zero ksum)
    cvt_all_kernel<<<(3 * NI4 + 4 * NW4) / 256, 256>>>(q, k, v, Wq, Wk, Wv, Wo,
                                                       XH, XL, WH, ks);

    // launch #1: Q + K projections only (256 CTAs -> single wave)
    proj_kernel<<<dim3(4, 32, 2), 256, SMP>>>(XH, XL, WH, bq, bk, bv,
                                              Qnh, Qnl, Kh, Vf, ks, 0);

    // fork after Q/K projections
    cudaEventRecord(evFork, 0);
    cudaStreamWaitEvent(s2, evFork, 0);

    // side chain on s2 (hidden under att): V projection -> spart -> s_reduce
    // launch #2
    proj_kernel<<<dim3(4, 32, 1), 256, SMP, s2>>>(XH, XL, WH, bq, bk, bv,
                                                  Qnh, Qnl, Kh, Vf, ks, 2);
    // launch #3
    spart_kernel<<<dim3(32, 16), 256, 0, s2>>>(Kh, ks, Vf, Spart);
    // launch #4
    s_reduce_kernel<<<64, 1024, 0, s2>>>(Spart, S);

    // launch #5 (profiled by ncu -s 5 -c 1): the big att GEMM on main stream
    att_kernel<<<dim3(16, 16, 16), 256, ATT_SMEM>>>(Qnh, Kh, ks, att);

    // launch #6, #7: rest of side chain
    oh_kernel<<<dim3(16, 16), 256, 0, s2>>>(Qnh, Qnl, S, OHh, OHl);
    mm2_kernel<<<dim3(4, 32, 1), 256, SMP, s2>>>(OHh, OHl, WH + 3LL * DM * DM, out, bo);
    cudaEventRecord(evJoin, s2);

    cudaStreamWaitEvent(0, evJoin, 0);
}

// round 11
// speedup vs baseline: 1.0946x; 1.0946x over previous
#include <cuda_runtime.h>
#include <cuda_fp16.h>
#include <cstdint>

#define NTOK   4096          // B*N = 2*2048
#define DM     512
#define NSEQ   2048
#define NHEADS 8
#define DK     64

#define QSCALE 64.0f
#define KSCALE 2048.0f
#define ATT_CSCALE (1.0f / (64.0f * 2048.0f))
#define OH_CSCALE  (1.0f / (64.0f * 2048.0f))

// ---------------- scratch (__device__ globals; no allocs allowed) ----------
__device__ float g_Vf[NTOK * DM];                             // V fp32
__device__ __half g_XH[3 * NTOK * DM], g_XL[3 * NTOK * DM];   // q,k,v hi/lo
__device__ __half g_WH[4 * DM * DM];                          // Wq,Wk,Wv,Wo (hi)
__device__ __half g_Qnh[NTOK * DM], g_Qnl[NTOK * DM];         // Qn * 64 (exact pair)
__device__ __half g_Kh[NTOK * DM];                            // elu(K)+1, fp16
__device__ float g_ksum[1024];                                // per (b, d) col sums
__device__ float g_Spart[32 * 16 * DK * DK];                  // scaled x2048
__device__ float g_S[16 * DK * DK];                           // scaled x2048
__device__ __half g_OHh[NTOK * DM], g_OHl[NTOK * DM];

// ---------------- helpers ---------------------------------------------------
__device__ __forceinline__ void cvt_split(float x, __half& hi, __half& lo) {
    hi = __float2half_rn(x);
    lo = __float2half_rn(x - __half2float(hi));
}
__device__ __forceinline__ uint32_t pack2(__half a, __half b) {
    __half2 t(a, b);
    return *reinterpret_cast<uint32_t*>(&t);
}
__device__ __forceinline__ uint32_t smem_u32(const void* p) {
    uint32_t a;
    asm("{ .reg .u64 t; cvta.to.shared.u64 t, %1; cvt.u32.u64 %0, t; }" : "=r"(a) : "l"(p));
    return a;
}
__device__ __forceinline__ void mma16816(float* c, const uint32_t* a, const uint32_t* b) {
    asm volatile(
        "mma.sync.aligned.m16n8k16.row.col.f32.f16.f16.f32 "
        "{%0,%1,%2,%3},{%4,%5,%6,%7},{%8,%9},{%0,%1,%2,%3};"
        : "+f"(c[0]), "+f"(c[1]), "+f"(c[2]), "+f"(c[3])
        : "r"(a[0]), "r"(a[1]), "r"(a[2]), "r"(a[3]), "r"(b[0]), "r"(b[1]));
}
__device__ __forceinline__ void ldsm4(uint32_t* r, uint32_t a) {
    asm volatile("ldmatrix.sync.aligned.m8n8.x4.shared.b16 {%0,%1,%2,%3},[%4];"
                 : "=r"(r[0]), "=r"(r[1]), "=r"(r[2]), "=r"(r[3]) : "r"(a));
}
__device__ __forceinline__ float elup1(float x) {
    return (x > 0.f) ? x + 1.f : expf(x);
}

// ---------------- one-shot fp32 -> fp16 conversion (inputs hi/lo, weights hi)
#define NI4 (NTOK * DM / 4)
#define NW4 (DM * DM / 4)

__global__ void cvt_all_kernel(const float* __restrict__ q, const float* __restrict__ k,
                               const float* __restrict__ v,
                               const float* __restrict__ Wq, const float* __restrict__ Wk,
                               const float* __restrict__ Wv, const float* __restrict__ Wo,
                               __half* __restrict__ XH, __half* __restrict__ XL,
                               __half* __restrict__ WH,
                               float* __restrict__ ksum)
{
    if (blockIdx.x < 4) ksum[blockIdx.x * 256 + threadIdx.x] = 0.f;
    long long i4 = (long long)blockIdx.x * 256 + threadIdx.x;
    float4 vv;
    if (i4 < 3LL * NI4) {
        int w = (int)(i4 / NI4);
        const float* src = (w == 0) ? q : (w == 1) ? k : v;
        long long off = i4;
        i4 -= (long long)w * NI4;
        vv = reinterpret_cast<const float4*>(src)[i4];
        __half a, b, c, d, e, f, g, hh;
        cvt_split(vv.x, a, e); cvt_split(vv.y, b, f);
        cvt_split(vv.z, c, g); cvt_split(vv.w, d, hh);
        uint2 ph; ph.x = pack2(a, b); ph.y = pack2(c, d);
        uint2 pl; pl.x = pack2(e, f); pl.y = pack2(g, hh);
        reinterpret_cast<uint2*>(XH)[off] = ph;
        reinterpret_cast<uint2*>(XL)[off] = pl;
    } else {
        long long j = i4 - 3LL * NI4;
        int w = (int)(j / NW4);
        const float* src = (w == 0) ? Wq : (w == 1) ? Wk : (w == 2) ? Wv : Wo;
        long long loc = j - (long long)w * NW4;
        vv = reinterpret_cast<const float4*>(src)[loc];
        uint2 ph;
        ph.x = pack2(__float2half_rn(vv.x), __float2half_rn(vv.y));
        ph.y = pack2(__float2half_rn(vv.z), __float2half_rn(vv.w));
        reinterpret_cast<uint2*>(WH)[j] = ph;
    }
}

// ---------------- shared GEMM plumbing --------------------------------------
#define GST   40                  // padded row: 32 elems + 8 (80B; LDSM conflict-free)
#define TILEB (128 * GST * 2)     // 10240 B per tile

// ---------------- fused projection kernel (z: 0=q,1=k,2=v) ------------------
__global__ __launch_bounds__(256, 2)
void proj_kernel(const __half* __restrict__ XH, const __half* __restrict__ XL,
                 const __half* __restrict__ WH,
                 const float* __restrict__ bq, const float* __restrict__ bk,
                 const float* __restrict__ bv,
                 __half* __restrict__ Qnh, __half* __restrict__ Qnl,
                 __half* __restrict__ Kh, float* __restrict__ Vf,
                 float* __restrict__ ksum)
{
    extern __shared__ __half smem[];
    constexpr int STAGEB = 3 * TILEB;
    int zb = blockIdx.z;
    const __half* Ahi = XH + (long long)zb * NTOK * DM;
    const __half* Alo = XL + (long long)zb * NTOK * DM;
    const __half* Bhi = WH + (long long)zb * DM * DM;
    const float* bias = (zb == 0) ? bq : (zb == 1) ? bk : bv;

    int m0 = blockIdx.y * 128, n0 = blockIdx.x * 128;
    int tid = threadIdx.x, lane = tid & 31, warp = tid >> 5;
    int wm = (warp >> 1) * 32;
    int wn = (warp & 1) * 64;
    int grp = lane >> 2, tig = lane & 3;
    uint32_t sb = smem_u32(smem);

    int aoff = (wm + (lane & 15)) * GST + ((lane >> 4) << 3);
    int boff = (wn + ((lane >> 4) << 3) + (lane & 7)) * GST + (((lane >> 3) & 1) << 3);

    float acc[2][8][4];
    #pragma unroll
    for (int i = 0; i < 2; i++)
        #pragma unroll
        for (int j = 0; j < 8; j++)
            #pragma unroll
            for (int l = 0; l < 4; l++) acc[i][j][l] = 0.f;

    auto issue = [&](int s, int kt) {
        #pragma unroll
        for (int j = 0; j < 6; j++) {
            int id = tid + j * 256;
            int tile = id >> 9;
            int w = id & 511;
            int r = w >> 2, ce = (w & 3) * 8;
            const __half* src;
            if (tile == 0)      src = Ahi + (long long)(m0 + r) * DM + kt + ce;
            else if (tile == 1) src = Alo + (long long)(m0 + r) * DM + kt + ce;
            else                src = Bhi + (long long)(n0 + r) * DM + kt + ce;
            uint32_t d = sb + (uint32_t)(s * STAGEB + tile * TILEB) + (uint32_t)(r * GST + ce) * 2u;
            asm volatile("cp.async.cg.shared.global [%0],[%1],16;\n" :: "r"(d), "l"(src));
        }
        asm volatile("cp.async.commit_group;\n" ::);
    };

    issue(0, 0);
    for (int i = 0; i < 16; i++) {
        int cur = i & 1;
        if (i + 1 < 16) {
            issue(cur ^ 1, (i + 1) << 5);
            asm volatile("cp.async.wait_group 1;\n" ::);
        } else {
            asm volatile("cp.async.wait_group 0;\n" ::);
        }
        __syncthreads();
        uint32_t sA  = sb + cur * STAGEB;
        uint32_t sAl = sA + TILEB;
        uint32_t sB  = sA + 2 * TILEB;

        #pragma unroll
        for (int kk = 0; kk < 32; kk += 16) {
            uint32_t ah[2][4], al[2][4], bf[4][4];
            #pragma unroll
            for (int mi = 0; mi < 2; mi++)
                ldsm4(ah[mi], sA + (uint32_t)(aoff + mi * 16 * GST + kk) * 2u);
            #pragma unroll
            for (int n2 = 0; n2 < 4; n2++)
                ldsm4(bf[n2], sB + (uint32_t)(boff + n2 * 16 * GST + kk) * 2u);
            #pragma unroll
            for (int mi = 0; mi < 2; mi++)
                #pragma unroll
                for (int n2 = 0; n2 < 4; n2++) {
                    mma16816(acc[mi][2 * n2],     ah[mi], bf[n2]);
                    mma16816(acc[mi][2 * n2 + 1], ah[mi], bf[n2] + 2);
                }
            #pragma unroll
            for (int mi = 0; mi < 2; mi++)
                ldsm4(al[mi], sAl + (uint32_t)(aoff + mi * 16 * GST + kk) * 2u);
            #pragma unroll
            for (int mi = 0; mi < 2; mi++)
                #pragma unroll
                for (int n2 = 0; n2 < 4; n2++) {
                    mma16816(acc[mi][2 * n2],     al[mi], bf[n2]);
                    mma16816(acc[mi][2 * n2 + 1], al[mi], bf[n2] + 2);
                }
        }
        __syncthreads();
    }

    // ---- epilogue: bias (+ elu+1 for q,k) ----
    #pragma unroll
    for (int mi = 0; mi < 2; mi++)
        #pragma unroll
        for (int ni = 0; ni < 8; ni++) {
            int col = n0 + wn + ni * 8 + tig * 2;
            float bb0 = __ldg(&bias[col]), bb1 = __ldg(&bias[col + 1]);
            acc[mi][ni][0] += bb0; acc[mi][ni][1] += bb1;
            acc[mi][ni][2] += bb0; acc[mi][ni][3] += bb1;
            if (zb < 2) {
                acc[mi][ni][0] = elup1(acc[mi][ni][0]);
                acc[mi][ni][1] = elup1(acc[mi][ni][1]);
                acc[mi][ni][2] = elup1(acc[mi][ni][2]);
                acc[mi][ni][3] = elup1(acc[mi][ni][3]);
            }
        }

    if (zb == 0) {
        #pragma unroll
        for (int mi = 0; mi < 2; mi++) {
            float s0 = 0.f, s1 = 0.f;
            #pragma unroll
            for (int ni = 0; ni < 8; ni++) {
                s0 += acc[mi][ni][0] + acc[mi][ni][1];
                s1 += acc[mi][ni][2] + acc[mi][ni][3];
            }
            s0 += __shfl_xor_sync(0xffffffffu, s0, 1);
            s0 += __shfl_xor_sync(0xffffffffu, s0, 2);
            s1 += __shfl_xor_sync(0xffffffffu, s1, 1);
            s1 += __shfl_xor_sync(0xffffffffu, s1, 2);
            float inv0 = QSCALE / (s0 + 1e-8f);
            float inv1 = QSCALE / (s1 + 1e-8f);
            int r0 = m0 + wm + mi * 16 + grp;
            #pragma unroll
            for (int ni = 0; ni < 8; ni++) {
                int col = n0 + wn + ni * 8 + tig * 2;
                __half h0, l0, h1, l1;
                cvt_split(acc[mi][ni][0] * inv0, h0, l0);
                cvt_split(acc[mi][ni][1] * inv0, h1, l1);
                *reinterpret_cast<uint32_t*>(&Qnh[(long long)r0 * DM + col]) = pack2(h0, h1);
                *reinterpret_cast<uint32_t*>(&Qnl[(long long)r0 * DM + col]) = pack2(l0, l1);
                cvt_split(acc[mi][ni][2] * inv1, h0, l0);
                cvt_split(acc[mi][ni][3] * inv1, h1, l1);
                *reinterpret_cast<uint32_t*>(&Qnh[(long long)(r0 + 8) * DM + col]) = pack2(h0, h1);
                *reinterpret_cast<uint32_t*>(&Qnl[(long long)(r0 + 8) * DM + col]) = pack2(l0, l1);
            }
        }
    } else if (zb == 1) {
        int bb = m0 >> 11;
        #pragma unroll
        for (int ni = 0; ni < 8; ni++) {
            int col = n0 + wn + ni * 8 + tig * 2;
            float c0 = 0.f, c1 = 0.f;
            #pragma unroll
            for (int mi = 0; mi < 2; mi++) {
                int r0 = m0 + wm + mi * 16 + grp;
                c0 += acc[mi][ni][0] + acc[mi][ni][2];
                c1 += acc[mi][ni][1] + acc[mi][ni][3];
                *reinterpret_cast<uint32_t*>(&Kh[(long long)r0 * DM + col]) =
                    pack2(__float2half_rn(acc[mi][ni][0]), __float2half_rn(acc[mi][ni][1]));
                *reinterpret_cast<uint32_t*>(&Kh[(long long)(r0 + 8) * DM + col]) =
                    pack2(__float2half_rn(acc[mi][ni][2]), __float2half_rn(acc[mi][ni][3]));
            }
            c0 += __shfl_xor_sync(0xffffffffu, c0, 4);
            c0 += __shfl_xor_sync(0xffffffffu, c0, 8);
            c0 += __shfl_xor_sync(0xffffffffu, c0, 16);
            c1 += __shfl_xor_sync(0xffffffffu, c1, 4);
            c1 += __shfl_xor_sync(0xffffffffu, c1, 8);
            c1 += __shfl_xor_sync(0xffffffffu, c1, 16);
            if (grp == 0) {
                atomicAdd(&ksum[bb * DM + col], c0);
                atomicAdd(&ksum[bb * DM + col + 1], c1);
            }
        }
    } else {
        #pragma unroll
        for (int mi = 0; mi < 2; mi++)
            #pragma unroll
            for (int ni = 0; ni < 8; ni++) {
                int row = m0 + wm + mi * 16 + grp;
                int col = n0 + wn + ni * 8 + tig * 2;
                *reinterpret_cast<float2*>(Vf + (long long)row * DM + col) =
                    make_float2(acc[mi][ni][0], acc[mi][ni][1]);
                *reinterpret_cast<float2*>(Vf + (long long)(row + 8) * DM + col) =
                    make_float2(acc[mi][ni][2], acc[mi][ni][3]);
            }
    }
}

// ---------------- final projection: out = OH @ Wo^T + bo (2-term) -----------
__global__ __launch_bounds__(256, 2)
void mm2_kernel(const __half* __restrict__ Ahi, const __half* __restrict__ Alo,
                const __half* __restrict__ Bhi,
                float* __restrict__ C,
                const float* __restrict__ bias)
{
    extern __shared__ __half smem[];
    constexpr int STAGEB = 3 * TILEB;

    int m0 = blockIdx.y * 128, n0 = blockIdx.x * 128;
    int tid = threadIdx.x, lane = tid & 31, warp = tid >> 5;
    int wm = (warp >> 1) * 32;
    int wn = (warp & 1) * 64;
    int grp = lane >> 2, tig = lane & 3;
    uint32_t sb = smem_u32(smem);

    int aoff = (wm + (lane & 15)) * GST + ((lane >> 4) << 3);
    int boff = (wn + ((lane >> 4) << 3) + (lane & 7)) * GST + (((lane >> 3) & 1) << 3);

    float acc[2][8][4];
    #pragma unroll
    for (int i = 0; i < 2; i++)
        #pragma unroll
        for (int j = 0; j < 8; j++)
            #pragma unroll
            for (int l = 0; l < 4; l++) acc[i][j][l] = 0.f;

    auto issue = [&](int s, int kt) {
        #pragma unroll
        for (int j = 0; j < 6; j++) {
            int id = tid + j * 256;
            int tile = id >> 9;
            int w = id & 511;
            int r = w >> 2, ce = (w & 3) * 8;
            const __half* src;
            if (tile == 0)      src = Ahi + (long long)(m0 + r) * DM + kt + ce;
            else if (tile == 1) src = Alo + (long long)(m0 + r) * DM + kt + ce;
            else                src = Bhi + (long long)(n0 + r) * DM + kt + ce;
            uint32_t d = sb + (uint32_t)(s * STAGEB + tile * TILEB) + (uint32_t)(r * GST + ce) * 2u;
            asm volatile("cp.async.cg.shared.global [%0],[%1],16;\n" :: "r"(d), "l"(src));
        }
        asm volatile("cp.async.commit_group;\n" ::);
    };

    issue(0, 0);
    for (int i = 0; i < 16; i++) {
        int cur = i & 1;
        if (i + 1 < 16) {
            issue(cur ^ 1, (i + 1) << 5);
            asm volatile("cp.async.wait_group 1;\n" ::);
        } else {
            asm volatile("cp.async.wait_group 0;\n" ::);
        }
        __syncthreads();
        uint32_t sA  = sb + cur * STAGEB;
        uint32_t sAl = sA + TILEB;
        uint32_t sB  = sA + 2 * TILEB;

        #pragma unroll
        for (int kk = 0; kk < 32; kk += 16) {
            uint32_t ah[2][4], al[2][4], bf[4][4];
            #pragma unroll
            for (int mi = 0; mi < 2; mi++)
                ldsm4(ah[mi], sA + (uint32_t)(aoff + mi * 16 * GST + kk) * 2u);
            #pragma unroll
            for (int n2 = 0; n2 < 4; n2++)
                ldsm4(bf[n2], sB + (uint32_t)(boff + n2 * 16 * GST + kk) * 2u);
            #pragma unroll
            for (int mi = 0; mi < 2; mi++)
                #pragma unroll
                for (int n2 = 0; n2 < 4; n2++) {
                    mma16816(acc[mi][2 * n2],     ah[mi], bf[n2]);
                    mma16816(acc[mi][2 * n2 + 1], ah[mi], bf[n2] + 2);
                }
            #pragma unroll
            for (int mi = 0; mi < 2; mi++)
                ldsm4(al[mi], sAl + (uint32_t)(aoff + mi * 16 * GST + kk) * 2u);
            #pragma unroll
            for (int mi = 0; mi < 2; mi++)
                #pragma unroll
                for (int n2 = 0; n2 < 4; n2++) {
                    mma16816(acc[mi][2 * n2],     al[mi], bf[n2]);
                    mma16816(acc[mi][2 * n2 + 1], al[mi], bf[n2] + 2);
                }
        }
        __syncthreads();
    }

    #pragma unroll
    for (int mi = 0; mi < 2; mi++) {
        #pragma unroll
        for (int ni = 0; ni < 8; ni++) {
            int row = m0 + wm + mi * 16 + grp;
            int col = n0 + wn + ni * 8 + tig * 2;
            float bb0 = __ldg(&bias[col]), bb1 = __ldg(&bias[col + 1]);
            float2 p0 = make_float2(acc[mi][ni][0] + bb0, acc[mi][ni][1] + bb1);
            float2 p1 = make_float2(acc[mi][ni][2] + bb0, acc[mi][ni][3] + bb1);
            __stcs(reinterpret_cast<float2*>(C + (long long)row * DM + col), p0);
            __stcs(reinterpret_cast<float2*>(C + (long long)(row + 8) * DM + col), p1);
        }
    }
}

// ---------------- att: K-resident blocked GEMM ------------------------------
// grid (16 n-tiles, 4 m-groups, 16 bh). Each CTA: load + normalize its K tile
// (128 rows x 64 k, two 32-k chunks) ONCE, then loop 4 M-tiles of Q
// (double-buffered cp.async), computing 128x128 per tile.
#define ATT_SMEM (6 * TILEB + 256)   // Kbuf(2) + Qstage(2 x 2 chunks) + sc

__global__ __launch_bounds__(256, 2)
void att_kernel(const __half* __restrict__ Qnh, const __half* __restrict__ Kh,
                const float* __restrict__ ksum, float* __restrict__ att)
{
    extern __shared__ char dsm[];
    int tid = threadIdx.x;
    int bh = blockIdx.z;
    int b = bh >> 3, h = bh & 7;
    const __half* A = Qnh + (long long)b * NSEQ * DM + h * DK;
    const __half* B = Kh + (long long)b * NSEQ * DM + h * DK;
    float* C = att + (long long)bh * NSEQ * NSEQ;
    float* sc = reinterpret_cast<float*>(dsm + 6 * TILEB);

    int n0 = blockIdx.x * 128;
    int mg = blockIdx.y;                   // m-group: rows mg*512 .. mg*512+511
    int lane = tid & 31, warp = tid >> 5;
    int wm = (warp >> 1) * 32;
    int wn = (warp & 1) * 64;
    int grp = lane >> 2, tig = lane & 3;
    uint32_t sb = smem_u32(dsm);
    constexpr uint32_t KOFF = 0;            // Kbuf: 2*TILEB
    constexpr uint32_t QOFF = 2 * TILEB;    // Qstage[s]: s*(2*TILEB), 2 chunks each

    int aoff = (wm + (lane & 15)) * GST + ((lane >> 4) << 3);
    int boff = (wn + ((lane >> 4) << 3) + (lane & 7)) * GST + (((lane >> 3) & 1) << 3);

    // issue the K tile (both 32-k chunks), 4 x 16B per thread
    auto issueK = [&]() {
        #pragma unroll
        for (int j = 0; j < 4; j++) {
            int id = tid + j * 256;
            int ch = id >> 9;
            int w = id & 511;
            int r = w >> 2, ce = (w & 3) * 8;
            const __half* src = B + (long long)(n0 + r) * DM + ch * 32 + ce;
            uint32_t d = sb + KOFF + (uint32_t)ch * TILEB + (uint32_t)(r * GST + ce) * 2u;
            asm volatile("cp.async.cg.shared.global [%0],[%1],16;\n" :: "r"(d), "l"(src));
        }
        asm volatile("cp.async.commit_group;\n" ::);
    };
    // issue one Q M-tile (both chunks) into stage s
    auto issueQ = [&](int s, int m0) {
        #pragma unroll
        for (int j = 0; j < 4; j++) {
            int id = tid + j * 256;
            int ch = id >> 9;
            int w = id & 511;
            int r = w >> 2, ce = (w & 3) * 8;
            const __half* src = A + (long long)(m0 + r) * DM + ch * 32 + ce;
            uint32_t d = sb + QOFF + (uint32_t)s * (2 * TILEB) + (uint32_t)ch * TILEB
                       + (uint32_t)(r * GST + ce) * 2u;
            asm volatile("cp.async.cg.shared.global [%0],[%1],16;\n" :: "r"(d), "l"(src));
        }
        asm volatile("cp.async.commit_group;\n" ::);
    };

    issueK();                               // group 0
    issueQ(0, mg * 512);                    // group 1
    if (tid < 64) sc[tid] = KSCALE / (__ldg(&ksum[b * DM + h * DK + tid]) + 1e-8f);
    asm volatile("cp.async.wait_group 1;\n" ::);   // K done
    __syncthreads();
    // normalize K tile in smem (both chunks): x KSCALE/ksum[d]
    #pragma unroll
    for (int j = 0; j < 16; j++) {
        int id = tid + j * 256;
        int ch = id >> 11;
        int w = id & 2047;
        int r = w >> 4, c = (w & 15) * 2;
        __half2* p = reinterpret_cast<__half2*>(dsm + KOFF + (uint32_t)ch * TILEB
                                                + (uint32_t)(r * GST + c) * 2u);
        float2 f = __half22float2(*p);
        f.x *= sc[ch * 32 + c];
        f.y *= sc[ch * 32 + c + 1];
        *p = __floats2half2_rn(f.x, f.y);
    }
    __syncthreads();

    for (int t = 0; t < 4; t++) {
        int cur = t & 1;
        if (t + 1 < 4) {
            issueQ(cur ^ 1, mg * 512 + (t + 1) * 128);
            asm volatile("cp.async.wait_group 1;\n" ::);
        } else {
            asm volatile("cp.async.wait_group 0;\n" ::);
        }
        __syncthreads();

        float acc[2][8][4];
        #pragma unroll
        for (int i = 0; i < 2; i++)
            #pragma unroll
            for (int j = 0; j < 8; j++)
                #pragma unroll
                for (int l = 0; l < 4; l++) acc[i][j][l] = 0.f;

        uint32_t qbase = sb + QOFF + (uint32_t)cur * (2 * TILEB);
        #pragma unroll
        for (int ch = 0; ch < 2; ch++) {
            uint32_t sA = qbase + (uint32_t)ch * TILEB;
            uint32_t sK = sb + KOFF + (uint32_t)ch * TILEB;
            #pragma unroll
            for (int kk = 0; kk < 32; kk += 16) {
                uint32_t ah[2][4], bf[4][4];
                #pragma unroll
                for (int mi = 0; mi < 2; mi++)
                    ldsm4(ah[mi], sA + (uint32_t)(aoff + mi * 16 * GST + kk) * 2u);
                #pragma unroll
                for (int n2 = 0; n2 < 4; n2++)
                    ldsm4(bf[n2], sK + (uint32_t)(boff + n2 * 16 * GST + kk) * 2u);
                #pragma unroll
                for (int mi = 0; mi < 2; mi++)
                    #pragma unroll
                    for (int n2 = 0; n2 < 4; n2++) {
                        mma16816(acc[mi][2 * n2],     ah[mi], bf[n2]);
                        mma16816(acc[mi][2 * n2 + 1], ah[mi], bf[n2] + 2);
                    }
            }
        }

        int m0 = mg * 512 + t * 128;
        #pragma unroll
        for (int mi = 0; mi < 2; mi++) {
            #pragma unroll
            for (int ni = 0; ni < 8; ni++) {
                int row = m0 + wm + mi * 16 + grp;
                int col = n0 + wn + ni * 8 + tig * 2;
                float2 p0 = make_float2(acc[mi][ni][0] * ATT_CSCALE, acc[mi][ni][1] * ATT_CSCALE);
                float2 p1 = make_float2(acc[mi][ni][2] * ATT_CSCALE, acc[mi][ni][3] * ATT_CSCALE);
                __stcs(reinterpret_cast<float2*>(C + (long long)row * NSEQ + col), p0);
                __stcs(reinterpret_cast<float2*>(C + (long long)(row + 8) * NSEQ + col), p1);
            }
        }
        __syncthreads();   // guard Qstage[cur] reuse by next prefetch
    }
}

// ---------------- spart: Kn^T V chunk partials (fp32 SIMT) ------------------
__global__ void spart_kernel(const __half* __restrict__ Kh, const float* __restrict__ ksum,
                             const float* __restrict__ Vf, float* __restrict__ Spart)
{
    __shared__ float Kt[64 * 64];
    __shared__ float Vt[64 * 64];
    __shared__ float sc[64];
    int chunk = blockIdx.x, bh = blockIdx.y;
    int b = bh >> 3, h = bh & 7;
    int tid = threadIdx.x;
    int d = tid & 63, qq = tid >> 6;
    if (tid < 64) sc[tid] = KSCALE / (__ldg(&ksum[b * DM + h * DK + tid]) + 1e-8f);
    __syncthreads();
    float acc[16];
    #pragma unroll
    for (int j = 0; j < 16; j++) acc[j] = 0.f;
    long long base = ((long long)b * NSEQ + chunk * 64) * DM + h * DK;
    #pragma unroll
    for (int j = 0; j < 16; j++) {
        int idd = tid + j * 256;
        int nl = idd >> 6, dd = idd & 63;
        Kt[nl * 64 + dd] = __half2float(Kh[base + (long long)nl * DM + dd]) * sc[dd];
        Vt[nl * 64 + dd] = Vf[base + (long long)nl * DM + dd];
    }
    __syncthreads();
    for (int nn = 0; nn < 64; nn++) {
        float kv = Kt[nn * 64 + d];
        const float4* vr = reinterpret_cast<const float4*>(&Vt[nn * 64 + qq * 16]);
        #pragma unroll
        for (int j4 = 0; j4 < 4; j4++) {
            float4 v = vr[j4];
            acc[j4 * 4 + 0] += kv * v.x;
            acc[j4 * 4 + 1] += kv * v.y;
            acc[j4 * 4 + 2] += kv * v.z;
            acc[j4 * 4 + 3] += kv * v.w;
        }
    }
    float* o = Spart + ((long long)chunk * 16 + bh) * (DK * DK) + d * DK + qq * 16;
    #pragma unroll
    for (int j4 = 0; j4 < 4; j4++)
        reinterpret_cast<float4*>(o)[j4] =
            make_float4(acc[j4 * 4], acc[j4 * 4 + 1], acc[j4 * 4 + 2], acc[j4 * 4 + 3]);
}

__global__ void s_reduce_kernel(const float* __restrict__ Spart, float* __restrict__ S) {
    int i = blockIdx.x * 1024 + threadIdx.x;
    float s = 0.f;
    #pragma unroll
    for (int c = 0; c < 32; c++) s += Spart[(long long)c * 65536 + i];
    S[i] = s;
}

// ---------------- OH = Qn @ S per (b,h) -------------------------------------
__global__ void oh_kernel(const __half* __restrict__ Qnh, const __half* __restrict__ Qnl,
                          const float* __restrict__ S,
                          __half* __restrict__ OHh, __half* __restrict__ OHl) {
    int mc = blockIdx.x;
    int bh = blockIdx.y;
    int b = bh >> 3, h = bh & 7;
    int t = threadIdx.x;
    int e4 = t & 15, r = t >> 4;
    __shared__ float Ss[64][64];
    __shared__ float Qs[16][64];
    #pragma unroll
    for (int j = 0; j < 16; j++) {
        int id = t + j * 256;
        Ss[id >> 6][id & 63] = S[(long long)bh * (DK * DK) + id];
    }
    for (int it = 0; it < 8; it++) {
        int mrow = mc * 128 + it * 16;
        __syncthreads();
        #pragma unroll
        for (int j = 0; j < 4; j++) {
            int id = t + j * 256;
            int rr = id >> 6, dd = id & 63;
            long long qidx = ((long long)b * NSEQ + mrow + rr) * DM + h * DK + dd;
            Qs[rr][dd] = __half2float(Qnh[qidx]) + __half2float(Qnl[qidx]);
        }
        __syncthreads();
        float4 a = make_float4(0.f, 0.f, 0.f, 0.f);
        #pragma unroll
        for (int dd = 0; dd < 64; dd++) {
            float qd = Qs[r][dd];
            float4 s4 = *reinterpret_cast<const float4*>(&Ss[dd][e4 * 4]);
            a.x += qd * s4.x; a.y += qd * s4.y; a.z += qd * s4.z; a.w += qd * s4.w;
        }
        __half h0, h1, h2, h3, l0, l1, l2, l3;
        cvt_split(a.x * OH_CSCALE, h0, l0); cvt_split(a.y * OH_CSCALE, h1, l1);
        cvt_split(a.z * OH_CSCALE, h2, l2); cvt_split(a.w * OH_CSCALE, h3, l3);
        long long oidx = ((long long)b * NSEQ + mrow + r) * DM + h * DK + e4 * 4;
        uint2 ph; ph.x = pack2(h0, h1); ph.y = pack2(h2, h3);
        uint2 pl; pl.x = pack2(l0, l1); pl.y = pack2(l2, l3);
        *reinterpret_cast<uint2*>(OHh + oidx) = ph;
        *reinterpret_cast<uint2*>(OHl + oidx) = pl;
    }
}

// ---------------- launch ----------------------------------------------------
extern "C" void kernel_launch(void* const* d_in, const int* in_sizes, int n_in,
                              void* d_out, int out_size) {
    const float* q  = (const float*)d_in[0];
    const float* k  = (const float*)d_in[1];
    const float* v  = (const float*)d_in[2];
    const float* Wq = (const float*)d_in[3];
    const float* bq = (const float*)d_in[4];
    const float* Wk = (const float*)d_in[5];
    const float* bk = (const float*)d_in[6];
    const float* Wv = (const float*)d_in[7];
    const float* bv = (const float*)d_in[8];
    const float* Wo = (const float*)d_in[9];
    const float* bo = (const float*)d_in[10];

    float* out = (float*)d_out;                       // [2,2048,512]
    float* att = out + (long long)NTOK * DM;          // [2,8,2048,2048]

    float *Vf, *ks, *Spart, *S;
    __half *XH, *XL, *WH, *Qnh, *Qnl, *Kh, *OHh, *OHl;
    cudaGetSymbolAddress((void**)&Vf, g_Vf);
    cudaGetSymbolAddress((void**)&ks, g_ksum);
    cudaGetSymbolAddress((void**)&Spart, g_Spart);
    cudaGetSymbolAddress((void**)&S, g_S);
    cudaGetSymbolAddress((void**)&XH, g_XH);  cudaGetSymbolAddress((void**)&XL, g_XL);
    cudaGetSymbolAddress((void**)&WH, g_WH);
    cudaGetSymbolAddress((void**)&Qnh, g_Qnh); cudaGetSymbolAddress((void**)&Qnl, g_Qnl);
    cudaGetSymbolAddress((void**)&Kh, g_Kh);
    cudaGetSymbolAddress((void**)&OHh, g_OHh); cudaGetSymbolAddress((void**)&OHl, g_OHl);

    constexpr int SMP = 2 * 3 * TILEB;   // 61440
    cudaFuncSetAttribute(proj_kernel, cudaFuncAttributeMaxDynamicSharedMemorySize, SMP);
    cudaFuncSetAttribute(mm2_kernel, cudaFuncAttributeMaxDynamicSharedMemorySize, SMP);
    cudaFuncSetAttribute(att_kernel, cudaFuncAttributeMaxDynamicSharedMemorySize, ATT_SMEM);

    static cudaStream_t s2 = nullptr;
    static cudaEvent_t evFork = nullptr, evJoin = nullptr;
    if (!s2) {
        cudaStreamCreateWithFlags(&s2, cudaStreamNonBlocking);
        cudaEventCreateWithFlags(&evFork, cudaEventDisableTiming);
        cudaEventCreateWithFlags(&evJoin, cudaEventDisableTiming);
    }

    // 0: one-shot conversions (+ zero ksum)
    cvt_all_kernel<<<(3 * NI4 + 4 * NW4) / 256, 256>>>(q, k, v, Wq, Wk, Wv, Wo,
                                                       XH, XL, WH, ks);

    // 1: fused projections: q->Qnh/Qnl (normalized), k->Kh + ksum, v->Vf
    proj_kernel<<<dim3(4, 32, 3), 256, SMP>>>(XH, XL, WH, bq, bk, bv,
                                              Qnh, Qnl, Kh, Vf, ks);

    // fork: side chain on s2, hidden under att
    cudaEventRecord(evFork, 0);
    cudaStreamWaitEvent(s2, evFork, 0);

    spart_kernel<<<dim3(32, 16), 256, 0, s2>>>(Kh, ks, Vf, Spart);
    s_reduce_kernel<<<64, 1024, 0, s2>>>(Spart, S);
    oh_kernel<<<dim3(16, 16), 256, 0, s2>>>(Qnh, Qnl, S, OHh, OHl);
    mm2_kernel<<<dim3(4, 32, 1), 256, SMP, s2>>>(OHh, OHl, WH + 3LL * DM * DM, out, bo);
    cudaEventRecord(evJoin, s2);

    // main: K-resident blocked att GEMM
    att_kernel<<<dim3(16, 4, 16), 256, ATT_SMEM>>>(Qnh, Kh, ks, att);

    cudaStreamWaitEvent(0, evJoin, 0);
}

// round 12
// speedup vs baseline: 1.2182x; 1.1129x over previous
#include <cuda_runtime.h>
#include <cuda_fp16.h>
#include <cstdint>

#define NTOK   4096          // B*N = 2*2048
#define DM     512
#define NSEQ   2048
#define NHEADS 8
#define DK     64

#define QSCALE 64.0f
#define KSCALE 2048.0f
#define ATT_CSCALE (1.0f / (64.0f * 2048.0f))
#define OH_CSCALE  (1.0f / (64.0f * 2048.0f))

// ---------------- scratch (__device__ globals; no allocs allowed) ----------
__device__ float g_Vf[NTOK * DM];                             // V fp32
__device__ __half g_XH[3 * NTOK * DM];                        // q,k,v (hi only)
__device__ __half g_WH[4 * DM * DM];                          // Wq,Wk,Wv,Wo (hi)
__device__ __half g_Qnh[NTOK * DM], g_Qnl[NTOK * DM];         // Qn * 64 (exact pair)
__device__ __half g_Kh[NTOK * DM];                            // elu(K)+1, fp16
__device__ float g_ksum[1024];                                // per (b, d) col sums
__device__ float g_Spart[32 * 16 * DK * DK];                  // scaled x2048
__device__ float g_S[16 * DK * DK];                           // scaled x2048
__device__ __half g_OHh[NTOK * DM], g_OHl[NTOK * DM];

// ---------------- helpers ---------------------------------------------------
__device__ __forceinline__ void cvt_split(float x, __half& hi, __half& lo) {
    hi = __float2half_rn(x);
    lo = __float2half_rn(x - __half2float(hi));
}
__device__ __forceinline__ uint32_t pack2(__half a, __half b) {
    __half2 t(a, b);
    return *reinterpret_cast<uint32_t*>(&t);
}
__device__ __forceinline__ uint32_t smem_u32(const void* p) {
    uint32_t a;
    asm("{ .reg .u64 t; cvta.to.shared.u64 t, %1; cvt.u32.u64 %0, t; }" : "=r"(a) : "l"(p));
    return a;
}
__device__ __forceinline__ void mma16816(float* c, const uint32_t* a, const uint32_t* b) {
    asm volatile(
        "mma.sync.aligned.m16n8k16.row.col.f32.f16.f16.f32 "
        "{%0,%1,%2,%3},{%4,%5,%6,%7},{%8,%9},{%0,%1,%2,%3};"
        : "+f"(c[0]), "+f"(c[1]), "+f"(c[2]), "+f"(c[3])
        : "r"(a[0]), "r"(a[1]), "r"(a[2]), "r"(a[3]), "r"(b[0]), "r"(b[1]));
}
__device__ __forceinline__ void ldsm4(uint32_t* r, uint32_t a) {
    asm volatile("ldmatrix.sync.aligned.m8n8.x4.shared.b16 {%0,%1,%2,%3},[%4];"
                 : "=r"(r[0]), "=r"(r[1]), "=r"(r[2]), "=r"(r[3]) : "r"(a));
}
__device__ __forceinline__ float elup1(float x) {
    return (x > 0.f) ? x + 1.f : expf(x);
}

// ---------------- one-shot fp32 -> fp16 conversion (hi only) ---------------
#define NI4 (NTOK * DM / 4)
#define NW4 (DM * DM / 4)

__global__ void cvt_all_kernel(const float* __restrict__ q, const float* __restrict__ k,
                               const float* __restrict__ v,
                               const float* __restrict__ Wq, const float* __restrict__ Wk,
                               const float* __restrict__ Wv, const float* __restrict__ Wo,
                               __half* __restrict__ XH, __half* __restrict__ WH,
                               float* __restrict__ ksum)
{
    if (blockIdx.x < 4) ksum[blockIdx.x * 256 + threadIdx.x] = 0.f;
    long long i4 = (long long)blockIdx.x * 256 + threadIdx.x;
    float4 vv;
    __half* dst;
    long long off;
    if (i4 < 3LL * NI4) {
        int w = (int)(i4 / NI4);
        const float* src = (w == 0) ? q : (w == 1) ? k : v;
        off = i4;
        vv = reinterpret_cast<const float4*>(src)[i4 - (long long)w * NI4];
        dst = XH;
    } else {
        long long j = i4 - 3LL * NI4;
        int w = (int)(j / NW4);
        const float* src = (w == 0) ? Wq : (w == 1) ? Wk : (w == 2) ? Wv : Wo;
        off = j;
        vv = reinterpret_cast<const float4*>(src)[j - (long long)w * NW4];
        dst = WH;
    }
    uint2 ph;
    ph.x = pack2(__float2half_rn(vv.x), __float2half_rn(vv.y));
    ph.y = pack2(__float2half_rn(vv.z), __float2half_rn(vv.w));
    reinterpret_cast<uint2*>(dst)[off] = ph;
}

// ---------------- shared GEMM plumbing --------------------------------------
#define GST   40                  // padded row: 32 elems + 8 (80B; LDSM conflict-free)
#define TILEB (128 * GST * 2)     // 10240 B per tile

// ---------------- fused projection kernel (1-term; z: 0=q,1=k,2=v) ----------
__global__ __launch_bounds__(256, 2)
void proj_kernel(const __half* __restrict__ XH, const __half* __restrict__ WH,
                 const float* __restrict__ bq, const float* __restrict__ bk,
                 const float* __restrict__ bv,
                 __half* __restrict__ Qnh, __half* __restrict__ Qnl,
                 __half* __restrict__ Kh, float* __restrict__ Vf,
                 float* __restrict__ ksum)
{
    extern __shared__ __half smem[];
    constexpr int STAGEB = 2 * TILEB;
    int zb = blockIdx.z;
    const __half* Ahi = XH + (long long)zb * NTOK * DM;
    const __half* Bhi = WH + (long long)zb * DM * DM;
    const float* bias = (zb == 0) ? bq : (zb == 1) ? bk : bv;

    int m0 = blockIdx.y * 128, n0 = blockIdx.x * 128;
    int tid = threadIdx.x, lane = tid & 31, warp = tid >> 5;
    int wm = (warp >> 1) * 32;
    int wn = (warp & 1) * 64;
    int grp = lane >> 2, tig = lane & 3;
    uint32_t sb = smem_u32(smem);

    int aoff = (wm + (lane & 15)) * GST + ((lane >> 4) << 3);
    int boff = (wn + ((lane >> 4) << 3) + (lane & 7)) * GST + (((lane >> 3) & 1) << 3);

    float acc[2][8][4];
    #pragma unroll
    for (int i = 0; i < 2; i++)
        #pragma unroll
        for (int j = 0; j < 8; j++)
            #pragma unroll
            for (int l = 0; l < 4; l++) acc[i][j][l] = 0.f;

    auto issue = [&](int s, int kt) {
        #pragma unroll
        for (int j = 0; j < 4; j++) {
            int id = tid + j * 256;
            int tile = id >> 9;
            int w = id & 511;
            int r = w >> 2, ce = (w & 3) * 8;
            const __half* src = (tile == 0)
                ? Ahi + (long long)(m0 + r) * DM + kt + ce
                : Bhi + (long long)(n0 + r) * DM + kt + ce;
            uint32_t d = sb + (uint32_t)(s * STAGEB + tile * TILEB) + (uint32_t)(r * GST + ce) * 2u;
            asm volatile("cp.async.cg.shared.global [%0],[%1],16;\n" :: "r"(d), "l"(src));
        }
        asm volatile("cp.async.commit_group;\n" ::);
    };

    issue(0, 0);
    for (int i = 0; i < 16; i++) {
        int cur = i & 1;
        if (i + 1 < 16) {
            issue(cur ^ 1, (i + 1) << 5);
            asm volatile("cp.async.wait_group 1;\n" ::);
        } else {
            asm volatile("cp.async.wait_group 0;\n" ::);
        }
        __syncthreads();
        uint32_t sA = sb + cur * STAGEB;
        uint32_t sB = sA + TILEB;

        #pragma unroll
        for (int kk = 0; kk < 32; kk += 16) {
            uint32_t ah[2][4], bf[4][4];
            #pragma unroll
            for (int mi = 0; mi < 2; mi++)
                ldsm4(ah[mi], sA + (uint32_t)(aoff + mi * 16 * GST + kk) * 2u);
            #pragma unroll
            for (int n2 = 0; n2 < 4; n2++)
                ldsm4(bf[n2], sB + (uint32_t)(boff + n2 * 16 * GST + kk) * 2u);
            #pragma unroll
            for (int mi = 0; mi < 2; mi++)
                #pragma unroll
                for (int n2 = 0; n2 < 4; n2++) {
                    mma16816(acc[mi][2 * n2],     ah[mi], bf[n2]);
                    mma16816(acc[mi][2 * n2 + 1], ah[mi], bf[n2] + 2);
                }
        }
        __syncthreads();
    }

    // ---- epilogue: bias (+ elu+1 for q,k) ----
    #pragma unroll
    for (int mi = 0; mi < 2; mi++)
        #pragma unroll
        for (int ni = 0; ni < 8; ni++) {
            int col = n0 + wn + ni * 8 + tig * 2;
            float bb0 = __ldg(&bias[col]), bb1 = __ldg(&bias[col + 1]);
            acc[mi][ni][0] += bb0; acc[mi][ni][1] += bb1;
            acc[mi][ni][2] += bb0; acc[mi][ni][3] += bb1;
            if (zb < 2) {
                acc[mi][ni][0] = elup1(acc[mi][ni][0]);
                acc[mi][ni][1] = elup1(acc[mi][ni][1]);
                acc[mi][ni][2] = elup1(acc[mi][ni][2]);
                acc[mi][ni][3] = elup1(acc[mi][ni][3]);
            }
        }

    if (zb == 0) {
        // Q: per-head row-normalize (warp's 64 cols = one full head)
        #pragma unroll
        for (int mi = 0; mi < 2; mi++) {
            float s0 = 0.f, s1 = 0.f;
            #pragma unroll
            for (int ni = 0; ni < 8; ni++) {
                s0 += acc[mi][ni][0] + acc[mi][ni][1];
                s1 += acc[mi][ni][2] + acc[mi][ni][3];
            }
            s0 += __shfl_xor_sync(0xffffffffu, s0, 1);
            s0 += __shfl_xor_sync(0xffffffffu, s0, 2);
            s1 += __shfl_xor_sync(0xffffffffu, s1, 1);
            s1 += __shfl_xor_sync(0xffffffffu, s1, 2);
            float inv0 = QSCALE / (s0 + 1e-8f);
            float inv1 = QSCALE / (s1 + 1e-8f);
            int r0 = m0 + wm + mi * 16 + grp;
            #pragma unroll
            for (int ni = 0; ni < 8; ni++) {
                int col = n0 + wn + ni * 8 + tig * 2;
                __half h0, l0, h1, l1;
                cvt_split(acc[mi][ni][0] * inv0, h0, l0);
                cvt_split(acc[mi][ni][1] * inv0, h1, l1);
                *reinterpret_cast<uint32_t*>(&Qnh[(long long)r0 * DM + col]) = pack2(h0, h1);
                *reinterpret_cast<uint32_t*>(&Qnl[(long long)r0 * DM + col]) = pack2(l0, l1);
                cvt_split(acc[mi][ni][2] * inv1, h0, l0);
                cvt_split(acc[mi][ni][3] * inv1, h1, l1);
                *reinterpret_cast<uint32_t*>(&Qnh[(long long)(r0 + 8) * DM + col]) = pack2(h0, h1);
                *reinterpret_cast<uint32_t*>(&Qnl[(long long)(r0 + 8) * DM + col]) = pack2(l0, l1);
            }
        }
    } else if (zb == 1) {
        // K: store fp16 + column-sum atomics
        int bb = m0 >> 11;
        #pragma unroll
        for (int ni = 0; ni < 8; ni++) {
            int col = n0 + wn + ni * 8 + tig * 2;
            float c0 = 0.f, c1 = 0.f;
            #pragma unroll
            for (int mi = 0; mi < 2; mi++) {
                int r0 = m0 + wm + mi * 16 + grp;
                c0 += acc[mi][ni][0] + acc[mi][ni][2];
                c1 += acc[mi][ni][1] + acc[mi][ni][3];
                *reinterpret_cast<uint32_t*>(&Kh[(long long)r0 * DM + col]) =
                    pack2(__float2half_rn(acc[mi][ni][0]), __float2half_rn(acc[mi][ni][1]));
                *reinterpret_cast<uint32_t*>(&Kh[(long long)(r0 + 8) * DM + col]) =
                    pack2(__float2half_rn(acc[mi][ni][2]), __float2half_rn(acc[mi][ni][3]));
            }
            c0 += __shfl_xor_sync(0xffffffffu, c0, 4);
            c0 += __shfl_xor_sync(0xffffffffu, c0, 8);
            c0 += __shfl_xor_sync(0xffffffffu, c0, 16);
            c1 += __shfl_xor_sync(0xffffffffu, c1, 4);
            c1 += __shfl_xor_sync(0xffffffffu, c1, 8);
            c1 += __shfl_xor_sync(0xffffffffu, c1, 16);
            if (grp == 0) {
                atomicAdd(&ksum[bb * DM + col], c0);
                atomicAdd(&ksum[bb * DM + col + 1], c1);
            }
        }
    } else {
        // V: fp32
        #pragma unroll
        for (int mi = 0; mi < 2; mi++)
            #pragma unroll
            for (int ni = 0; ni < 8; ni++) {
                int row = m0 + wm + mi * 16 + grp;
                int col = n0 + wn + ni * 8 + tig * 2;
                *reinterpret_cast<float2*>(Vf + (long long)row * DM + col) =
                    make_float2(acc[mi][ni][0], acc[mi][ni][1]);
                *reinterpret_cast<float2*>(Vf + (long long)(row + 8) * DM + col) =
                    make_float2(acc[mi][ni][2], acc[mi][ni][3]);
            }
    }
}

// ---------------- final projection: out = OH @ Wo^T + bo (2-term) -----------
__global__ __launch_bounds__(256, 2)
void mm2_kernel(const __half* __restrict__ Ahi, const __half* __restrict__ Alo,
                const __half* __restrict__ Bhi,
                float* __restrict__ C,
                const float* __restrict__ bias)
{
    extern __shared__ __half smem[];
    constexpr int STAGEB = 3 * TILEB;

    int m0 = blockIdx.y * 128, n0 = blockIdx.x * 128;
    int tid = threadIdx.x, lane = tid & 31, warp = tid >> 5;
    int wm = (warp >> 1) * 32;
    int wn = (warp & 1) * 64;
    int grp = lane >> 2, tig = lane & 3;
    uint32_t sb = smem_u32(smem);

    int aoff = (wm + (lane & 15)) * GST + ((lane >> 4) << 3);
    int boff = (wn + ((lane >> 4) << 3) + (lane & 7)) * GST + (((lane >> 3) & 1) << 3);

    float acc[2][8][4];
    #pragma unroll
    for (int i = 0; i < 2; i++)
        #pragma unroll
        for (int j = 0; j < 8; j++)
            #pragma unroll
            for (int l = 0; l < 4; l++) acc[i][j][l] = 0.f;

    auto issue = [&](int s, int kt) {
        #pragma unroll
        for (int j = 0; j < 6; j++) {
            int id = tid + j * 256;
            int tile = id >> 9;
            int w = id & 511;
            int r = w >> 2, ce = (w & 3) * 8;
            const __half* src;
            if (tile == 0)      src = Ahi + (long long)(m0 + r) * DM + kt + ce;
            else if (tile == 1) src = Alo + (long long)(m0 + r) * DM + kt + ce;
            else                src = Bhi + (long long)(n0 + r) * DM + kt + ce;
            uint32_t d = sb + (uint32_t)(s * STAGEB + tile * TILEB) + (uint32_t)(r * GST + ce) * 2u;
            asm volatile("cp.async.cg.shared.global [%0],[%1],16;\n" :: "r"(d), "l"(src));
        }
        asm volatile("cp.async.commit_group;\n" ::);
    };

    issue(0, 0);
    for (int i = 0; i < 16; i++) {
        int cur = i & 1;
        if (i + 1 < 16) {
            issue(cur ^ 1, (i + 1) << 5);
            asm volatile("cp.async.wait_group 1;\n" ::);
        } else {
            asm volatile("cp.async.wait_group 0;\n" ::);
        }
        __syncthreads();
        uint32_t sA  = sb + cur * STAGEB;
        uint32_t sAl = sA + TILEB;
        uint32_t sB  = sA + 2 * TILEB;

        #pragma unroll
        for (int kk = 0; kk < 32; kk += 16) {
            uint32_t ah[2][4], al[2][4], bf[4][4];
            #pragma unroll
            for (int mi = 0; mi < 2; mi++)
                ldsm4(ah[mi], sA + (uint32_t)(aoff + mi * 16 * GST + kk) * 2u);
            #pragma unroll
            for (int n2 = 0; n2 < 4; n2++)
                ldsm4(bf[n2], sB + (uint32_t)(boff + n2 * 16 * GST + kk) * 2u);
            #pragma unroll
            for (int mi = 0; mi < 2; mi++)
                #pragma unroll
                for (int n2 = 0; n2 < 4; n2++) {
                    mma16816(acc[mi][2 * n2],     ah[mi], bf[n2]);
                    mma16816(acc[mi][2 * n2 + 1], ah[mi], bf[n2] + 2);
                }
            #pragma unroll
            for (int mi = 0; mi < 2; mi++)
                ldsm4(al[mi], sAl + (uint32_t)(aoff + mi * 16 * GST + kk) * 2u);
            #pragma unroll
            for (int mi = 0; mi < 2; mi++)
                #pragma unroll
                for (int n2 = 0; n2 < 4; n2++) {
                    mma16816(acc[mi][2 * n2],     al[mi], bf[n2]);
                    mma16816(acc[mi][2 * n2 + 1], al[mi], bf[n2] + 2);
                }
        }
        __syncthreads();
    }

    #pragma unroll
    for (int mi = 0; mi < 2; mi++) {
        #pragma unroll
        for (int ni = 0; ni < 8; ni++) {
            int row = m0 + wm + mi * 16 + grp;
            int col = n0 + wn + ni * 8 + tig * 2;
            float bb0 = __ldg(&bias[col]), bb1 = __ldg(&bias[col + 1]);
            float2 p0 = make_float2(acc[mi][ni][0] + bb0, acc[mi][ni][1] + bb1);
            float2 p1 = make_float2(acc[mi][ni][2] + bb0, acc[mi][ni][3] + bb1);
            __stcs(reinterpret_cast<float2*>(C + (long long)row * DM + col), p0);
            __stcs(reinterpret_cast<float2*>(C + (long long)(row + 8) * DM + col), p1);
        }
    }
}

// ---------------- att: K-resident blocked GEMM ------------------------------
#define ATT_SMEM (6 * TILEB + 256)   // Kbuf(2) + Qstage(2 x 2 chunks) + sc

__global__ __launch_bounds__(256, 2)
void att_kernel(const __half* __restrict__ Qnh, const __half* __restrict__ Kh,
                const float* __restrict__ ksum, float* __restrict__ att)
{
    extern __shared__ char dsm[];
    int tid = threadIdx.x;
    int bh = blockIdx.z;
    int b = bh >> 3, h = bh & 7;
    const __half* A = Qnh + (long long)b * NSEQ * DM + h * DK;
    const __half* B = Kh + (long long)b * NSEQ * DM + h * DK;
    float* C = att + (long long)bh * NSEQ * NSEQ;
    float* sc = reinterpret_cast<float*>(dsm + 6 * TILEB);

    int n0 = blockIdx.x * 128;
    int mg = blockIdx.y;
    int lane = tid & 31, warp = tid >> 5;
    int wm = (warp >> 1) * 32;
    int wn = (warp & 1) * 64;
    int grp = lane >> 2, tig = lane & 3;
    uint32_t sb = smem_u32(dsm);
    constexpr uint32_t KOFF = 0;
    constexpr uint32_t QOFF = 2 * TILEB;

    int aoff = (wm + (lane & 15)) * GST + ((lane >> 4) << 3);
    int boff = (wn + ((lane >> 4) << 3) + (lane & 7)) * GST + (((lane >> 3) & 1) << 3);

    auto issueK = [&]() {
        #pragma unroll
        for (int j = 0; j < 4; j++) {
            int id = tid + j * 256;
            int ch = id >> 9;
            int w = id & 511;
            int r = w >> 2, ce = (w & 3) * 8;
            const __half* src = B + (long long)(n0 + r) * DM + ch * 32 + ce;
            uint32_t d = sb + KOFF + (uint32_t)ch * TILEB + (uint32_t)(r * GST + ce) * 2u;
            asm volatile("cp.async.cg.shared.global [%0],[%1],16;\n" :: "r"(d), "l"(src));
        }
        asm volatile("cp.async.commit_group;\n" ::);
    };
    auto issueQ = [&](int s, int m0) {
        #pragma unroll
        for (int j = 0; j < 4; j++) {
            int id = tid + j * 256;
            int ch = id >> 9;
            int w = id & 511;
            int r = w >> 2, ce = (w & 3) * 8;
            const __half* src = A + (long long)(m0 + r) * DM + ch * 32 + ce;
            uint32_t d = sb + QOFF + (uint32_t)s * (2 * TILEB) + (uint32_t)ch * TILEB
                       + (uint32_t)(r * GST + ce) * 2u;
            asm volatile("cp.async.cg.shared.global [%0],[%1],16;\n" :: "r"(d), "l"(src));
        }
        asm volatile("cp.async.commit_group;\n" ::);
    };

    issueK();
    issueQ(0, mg * 512);
    if (tid < 64) sc[tid] = KSCALE / (__ldg(&ksum[b * DM + h * DK + tid]) + 1e-8f);
    asm volatile("cp.async.wait_group 1;\n" ::);
    __syncthreads();
    #pragma unroll
    for (int j = 0; j < 16; j++) {
        int id = tid + j * 256;
        int ch = id >> 11;
        int w = id & 2047;
        int r = w >> 4, c = (w & 15) * 2;
        __half2* p = reinterpret_cast<__half2*>(dsm + KOFF + (uint32_t)ch * TILEB
                                                + (uint32_t)(r * GST + c) * 2u);
        float2 f = __half22float2(*p);
        f.x *= sc[ch * 32 + c];
        f.y *= sc[ch * 32 + c + 1];
        *p = __floats2half2_rn(f.x, f.y);
    }
    __syncthreads();

    for (int t = 0; t < 4; t++) {
        int cur = t & 1;
        if (t + 1 < 4) {
            issueQ(cur ^ 1, mg * 512 + (t + 1) * 128);
            asm volatile("cp.async.wait_group 1;\n" ::);
        } else {
            asm volatile("cp.async.wait_group 0;\n" ::);
        }
        __syncthreads();

        float acc[2][8][4];
        #pragma unroll
        for (int i = 0; i < 2; i++)
            #pragma unroll
            for (int j = 0; j < 8; j++)
                #pragma unroll
                for (int l = 0; l < 4; l++) acc[i][j][l] = 0.f;

        uint32_t qbase = sb + QOFF + (uint32_t)cur * (2 * TILEB);
        #pragma unroll
        for (int ch = 0; ch < 2; ch++) {
            uint32_t sA = qbase + (uint32_t)ch * TILEB;
            uint32_t sK = sb + KOFF + (uint32_t)ch * TILEB;
            #pragma unroll
            for (int kk = 0; kk < 32; kk += 16) {
                uint32_t ah[2][4], bf[4][4];
                #pragma unroll
                for (int mi = 0; mi < 2; mi++)
                    ldsm4(ah[mi], sA + (uint32_t)(aoff + mi * 16 * GST + kk) * 2u);
                #pragma unroll
                for (int n2 = 0; n2 < 4; n2++)
                    ldsm4(bf[n2], sK + (uint32_t)(boff + n2 * 16 * GST + kk) * 2u);
                #pragma unroll
                for (int mi = 0; mi < 2; mi++)
                    #pragma unroll
                    for (int n2 = 0; n2 < 4; n2++) {
                        mma16816(acc[mi][2 * n2],     ah[mi], bf[n2]);
                        mma16816(acc[mi][2 * n2 + 1], ah[mi], bf[n2] + 2);
                    }
            }
        }

        int m0 = mg * 512 + t * 128;
        #pragma unroll
        for (int mi = 0; mi < 2; mi++) {
            #pragma unroll
            for (int ni = 0; ni < 8; ni++) {
                int row = m0 + wm + mi * 16 + grp;
                int col = n0 + wn + ni * 8 + tig * 2;
                float2 p0 = make_float2(acc[mi][ni][0] * ATT_CSCALE, acc[mi][ni][1] * ATT_CSCALE);
                float2 p1 = make_float2(acc[mi][ni][2] * ATT_CSCALE, acc[mi][ni][3] * ATT_CSCALE);
                __stcs(reinterpret_cast<float2*>(C + (long long)row * NSEQ + col), p0);
                __stcs(reinterpret_cast<float2*>(C + (long long)(row + 8) * NSEQ + col), p1);
            }
        }
        __syncthreads();
    }
}

// ---------------- spart: Kn^T V chunk partials (fp32 SIMT) ------------------
__global__ void spart_kernel(const __half* __restrict__ Kh, const float* __restrict__ ksum,
                             const float* __restrict__ Vf, float* __restrict__ Spart)
{
    __shared__ float Kt[64 * 64];
    __shared__ float Vt[64 * 64];
    __shared__ float sc[64];
    int chunk = blockIdx.x, bh = blockIdx.y;
    int b = bh >> 3, h = bh & 7;
    int tid = threadIdx.x;
    int d = tid & 63, qq = tid >> 6;
    if (tid < 64) sc[tid] = KSCALE / (__ldg(&ksum[b * DM + h * DK + tid]) + 1e-8f);
    __syncthreads();
    float acc[16];
    #pragma unroll
    for (int j = 0; j < 16; j++) acc[j] = 0.f;
    long long base = ((long long)b * NSEQ + chunk * 64) * DM + h * DK;
    #pragma unroll
    for (int j = 0; j < 16; j++) {
        int idd = tid + j * 256;
        int nl = idd >> 6, dd = idd & 63;
        Kt[nl * 64 + dd] = __half2float(Kh[base + (long long)nl * DM + dd]) * sc[dd];
        Vt[nl * 64 + dd] = Vf[base + (long long)nl * DM + dd];
    }
    __syncthreads();
    for (int nn = 0; nn < 64; nn++) {
        float kv = Kt[nn * 64 + d];
        const float4* vr = reinterpret_cast<const float4*>(&Vt[nn * 64 + qq * 16]);
        #pragma unroll
        for (int j4 = 0; j4 < 4; j4++) {
            float4 v = vr[j4];
            acc[j4 * 4 + 0] += kv * v.x;
            acc[j4 * 4 + 1] += kv * v.y;
            acc[j4 * 4 + 2] += kv * v.z;
            acc[j4 * 4 + 3] += kv * v.w;
        }
    }
    float* o = Spart + ((long long)chunk * 16 + bh) * (DK * DK) + d * DK + qq * 16;
    #pragma unroll
    for (int j4 = 0; j4 < 4; j4++)
        reinterpret_cast<float4*>(o)[j4] =
            make_float4(acc[j4 * 4], acc[j4 * 4 + 1], acc[j4 * 4 + 2], acc[j4 * 4 + 3]);
}

__global__ void s_reduce_kernel(const float* __restrict__ Spart, float* __restrict__ S) {
    int i = blockIdx.x * 1024 + threadIdx.x;
    float s = 0.f;
    #pragma unroll
    for (int c = 0; c < 32; c++) s += Spart[(long long)c * 65536 + i];
    S[i] = s;
}

// ---------------- OH = Qn @ S per (b,h) -------------------------------------
__global__ void oh_kernel(const __half* __restrict__ Qnh, const __half* __restrict__ Qnl,
                          const float* __restrict__ S,
                          __half* __restrict__ OHh, __half* __restrict__ OHl) {
    int mc = blockIdx.x;
    int bh = blockIdx.y;
    int b = bh >> 3, h = bh & 7;
    int t = threadIdx.x;
    int e4 = t & 15, r = t >> 4;
    __shared__ float Ss[64][64];
    __shared__ float Qs[16][64];
    #pragma unroll
    for (int j = 0; j < 16; j++) {
        int id = t + j * 256;
        Ss[id >> 6][id & 63] = S[(long long)bh * (DK * DK) + id];
    }
    for (int it = 0; it < 8; it++) {
        int mrow = mc * 128 + it * 16;
        __syncthreads();
        #pragma unroll
        for (int j = 0; j < 4; j++) {
            int id = t + j * 256;
            int rr = id >> 6, dd = id & 63;
            long long qidx = ((long long)b * NSEQ + mrow + rr) * DM + h * DK + dd;
            Qs[rr][dd] = __half2float(Qnh[qidx]) + __half2float(Qnl[qidx]);
        }
        __syncthreads();
        float4 a = make_float4(0.f, 0.f, 0.f, 0.f);
        #pragma unroll
        for (int dd = 0; dd < 64; dd++) {
            float qd = Qs[r][dd];
            float4 s4 = *reinterpret_cast<const float4*>(&Ss[dd][e4 * 4]);
            a.x += qd * s4.x; a.y += qd * s4.y; a.z += qd * s4.z; a.w += qd * s4.w;
        }
        __half h0, h1, h2, h3, l0, l1, l2, l3;
        cvt_split(a.x * OH_CSCALE, h0, l0); cvt_split(a.y * OH_CSCALE, h1, l1);
        cvt_split(a.z * OH_CSCALE, h2, l2); cvt_split(a.w * OH_CSCALE, h3, l3);
        long long oidx = ((long long)b * NSEQ + mrow + r) * DM + h * DK + e4 * 4;
        uint2 ph; ph.x = pack2(h0, h1); ph.y = pack2(h2, h3);
        uint2 pl; pl.x = pack2(l0, l1); pl.y = pack2(l2, l3);
        *reinterpret_cast<uint2*>(OHh + oidx) = ph;
        *reinterpret_cast<uint2*>(OHl + oidx) = pl;
    }
}

// ---------------- launch ----------------------------------------------------
extern "C" void kernel_launch(void* const* d_in, const int* in_sizes, int n_in,
                              void* d_out, int out_size) {
    const float* q  = (const float*)d_in[0];
    const float* k  = (const float*)d_in[1];
    const float* v  = (const float*)d_in[2];
    const float* Wq = (const float*)d_in[3];
    const float* bq = (const float*)d_in[4];
    const float* Wk = (const float*)d_in[5];
    const float* bk = (const float*)d_in[6];
    const float* Wv = (const float*)d_in[7];
    const float* bv = (const float*)d_in[8];
    const float* Wo = (const float*)d_in[9];
    const float* bo = (const float*)d_in[10];

    float* out = (float*)d_out;                       // [2,2048,512]
    float* att = out + (long long)NTOK * DM;          // [2,8,2048,2048]

    float *Vf, *ks, *Spart, *S;
    __half *XH, *WH, *Qnh, *Qnl, *Kh, *OHh, *OHl;
    cudaGetSymbolAddress((void**)&Vf, g_Vf);
    cudaGetSymbolAddress((void**)&ks, g_ksum);
    cudaGetSymbolAddress((void**)&Spart, g_Spart);
    cudaGetSymbolAddress((void**)&S, g_S);
    cudaGetSymbolAddress((void**)&XH, g_XH);
    cudaGetSymbolAddress((void**)&WH, g_WH);
    cudaGetSymbolAddress((void**)&Qnh, g_Qnh); cudaGetSymbolAddress((void**)&Qnl, g_Qnl);
    cudaGetSymbolAddress((void**)&Kh, g_Kh);
    cudaGetSymbolAddress((void**)&OHh, g_OHh); cudaGetSymbolAddress((void**)&OHl, g_OHl);

    constexpr int SMP1 = 2 * 2 * TILEB;   // 40960 (1-term proj)
    constexpr int SMP2 = 2 * 3 * TILEB;   // 61440 (2-term mm2)
    cudaFuncSetAttribute(proj_kernel, cudaFuncAttributeMaxDynamicSharedMemorySize, SMP1);
    cudaFuncSetAttribute(mm2_kernel, cudaFuncAttributeMaxDynamicSharedMemorySize, SMP2);
    cudaFuncSetAttribute(att_kernel, cudaFuncAttributeMaxDynamicSharedMemorySize, ATT_SMEM);

    static cudaStream_t s2 = nullptr;
    static cudaEvent_t evFork = nullptr, evJoin = nullptr;
    if (!s2) {
        cudaStreamCreateWithFlags(&s2, cudaStreamNonBlocking);
        cudaEventCreateWithFlags(&evFork, cudaEventDisableTiming);
        cudaEventCreateWithFlags(&evJoin, cudaEventDisableTiming);
    }

    // 0: one-shot conversions (+ zero ksum)
    cvt_all_kernel<<<(3 * NI4 + 4 * NW4) / 256, 256>>>(q, k, v, Wq, Wk, Wv, Wo,
                                                       XH, WH, ks);

    // 1: fused 1-term projections: q->Qnh/Qnl (normalized), k->Kh + ksum, v->Vf
    proj_kernel<<<dim3(4, 32, 3), 256, SMP1>>>(XH, WH, bq, bk, bv,
                                               Qnh, Qnl, Kh, Vf, ks);

    // fork: side chain on s2, hidden under att
    cudaEventRecord(evFork, 0);
    cudaStreamWaitEvent(s2, evFork, 0);

    spart_kernel<<<dim3(32, 16), 256, 0, s2>>>(Kh, ks, Vf, Spart);
    s_reduce_kernel<<<64, 1024, 0, s2>>>(Spart, S);
    oh_kernel<<<dim3(16, 16), 256, 0, s2>>>(Qnh, Qnl, S, OHh, OHl);
    mm2_kernel<<<dim3(4, 32, 1), 256, SMP2, s2>>>(OHh, OHl, WH + 3LL * DM * DM, out, bo);
    cudaEventRecord(evJoin, s2);

    // main: K-resident blocked att GEMM
    att_kernel<<<dim3(16, 4, 16), 256, ATT_SMEM>>>(Qnh, Kh, ks, att);

    cudaStreamWaitEvent(0, evJoin, 0);
}